// round 9
// baseline (speedup 1.0000x reference)
#include <cuda_runtime.h>
#include <cstdint>
#include <cstdio>

#define B_ 64
#define S_ 64
#define P_ 32
#define D_ 512
#define E_ 512
#define H_ 512
#define H3_ 1536
#define A_ 256
#define NH_ 4
#define OUT_ 16
#define BS_ (B_*S_)

// d_out layout: out[64,16] | states[B,S,2H] | context[B,4096] | alpha_actv[B,NH,S]
#define STATES_OFF 1024
#define CONTEXT_OFF (1024 + BS_*2*H_)
#define ALPHA_OFF (CONTEXT_OFF + B_*NH_*2*H_)

// ---------------- scratch (device globals; no allocation allowed) -------------
__device__ float g_vec[BS_*D_];
__device__ float g_emb[BS_*E_];
__device__ float g_xg[2][BS_*H3_];
__device__ float g_h2[2][2][B_*H_];     // [dir][buf][b*H+j] (fallback path only)
__device__ float g_m1[BS_*A_];
__device__ unsigned g_cnt8[8][32];      // 8 barrier groups, padded (fallback)
__device__ unsigned g_gen8[8][32];

typedef unsigned long long ull;

// ---------------- f32x2 helpers (FFMA2: 2x fp32 FMA throughput) ---------------
__device__ __forceinline__ ull pk2(float x){
    ull r;
    asm("mov.b64 %0, {%1, %1};" : "=l"(r) : "f"(x));
    return r;
}
__device__ __forceinline__ void fma2(ull& d, ull a, ull b){
    asm("fma.rn.f32x2 %0, %1, %2, %0;" : "+l"(d) : "l"(a), "l"(b));
}
union U64F2 { ull u; float2 f; };

__device__ __forceinline__ uint32_t smem_u32(const void* p){
    uint32_t a;
    asm("{ .reg .u64 t; cvta.to.shared.u64 t, %1; cvt.u32.u64 %0, t; }"
        : "=r"(a) : "l"(p));
    return a;
}

// ---------------- simple group grid barrier (16 blocks per group, R6-proven) --
__device__ __forceinline__ void gbar_grp(int grp){
    __syncthreads();
    if (threadIdx.x == 0){
        __threadfence();
        unsigned g = *((volatile unsigned*)&g_gen8[grp][0]);
        if (atomicAdd(&g_cnt8[grp][0], 1u) == 15u){
            g_cnt8[grp][0] = 0u;
            __threadfence();
            atomicExch(&g_gen8[grp][0], g + 1u);
        } else {
            while (*((volatile unsigned*)&g_gen8[grp][0]) == g) { }
        }
        __threadfence();
    }
    __syncthreads();
}

// ---------------- fused conv + weighted-sum (reads inputs ONCE) ---------------
__global__ __launch_bounds__(256) void k_conv_vec(const float* __restrict__ inp,
                                                  const float* __restrict__ conv_w,
                                                  const float* __restrict__ conv_b){
    extern __shared__ float tile[];          // P_*D_ = 16384 floats = 64KB
    __shared__ float cw[D_];
    __shared__ float convp[P_];
    int bs = blockIdx.x;
    int tid = threadIdx.x;
    const float4* src4 = (const float4*)(inp + (size_t)bs*P_*D_);
    float4* t4 = (float4*)tile;
    for (int i = tid; i < D_; i += 256) cw[i] = conv_w[i];
    for (int i = tid; i < P_*D_/4; i += 256) t4[i] = src4[i];
    __syncthreads();
    int wid = tid >> 5, lane = tid & 31;
    float cb = conv_b[0];
    for (int p = wid; p < P_; p += 8){
        float s = 0.f;
        for (int d = lane; d < D_; d += 32) s += tile[p*D_+d]*cw[d];
        #pragma unroll
        for (int o = 16; o > 0; o >>= 1) s += __shfl_xor_sync(0xffffffffu, s, o);
        if (lane == 0) convp[p] = s + cb;
    }
    __syncthreads();
    for (int d = tid; d < D_; d += 256){
        float acc = 0.f;
        #pragma unroll
        for (int p = 0; p < P_; p++) acc += convp[p]*tile[p*D_+d];
        g_vec[(size_t)bs*D_ + d] = acc;
    }
}

// ---------------- SGEMM (R6-proven): C = A * Bw^T, optional z-select ----------
__global__ __launch_bounds__(256, 2) void k_sgemm(const float* __restrict__ A,
                                                  const float* __restrict__ Bw,
                                                  const float* __restrict__ Bw2,
                                                  float* __restrict__ C,
                                                  int M, int N, int K,
                                                  const float* __restrict__ bias,
                                                  const float* __restrict__ bias2,
                                                  int doClip, int permA){
    __shared__ float As[2][8][128];
    __shared__ float Bs[2][8][128];
    int tid = threadIdx.x;
    int bx = blockIdx.x, by = blockIdx.y;
    if (blockIdx.z){ Bw = Bw2; bias = bias2; C += (size_t)M*N; }
    int arow = tid >> 1;
    int acol = (tid & 1) * 4;
    int orow = by*128 + arow;
    int grow = permA ? ((orow & 63)*64 + (orow >> 6)) : orow;
    const float* Ap = A + (size_t)grow*K + acol;
    const float* Bp = Bw + (size_t)(bx*128 + arow)*K + acol;

    float4 av = *(const float4*)Ap;
    float4 bv = *(const float4*)Bp;
    As[0][acol+0][arow]=av.x; As[0][acol+1][arow]=av.y; As[0][acol+2][arow]=av.z; As[0][acol+3][arow]=av.w;
    Bs[0][acol+0][arow]=bv.x; Bs[0][acol+1][arow]=bv.y; Bs[0][acol+2][arow]=bv.z; Bs[0][acol+3][arow]=bv.w;
    __syncthreads();

    int tx = tid & 15, ty = tid >> 4;
    ull acc[8][4];
    #pragma unroll
    for (int i = 0; i < 8; i++){
        #pragma unroll
        for (int j = 0; j < 4; j++) acc[i][j] = 0ULL;
    }

    int nk = K >> 3;
    for (int kt = 0; kt < nk; kt++){
        int cur = kt & 1;
        if (kt + 1 < nk){
            av = *(const float4*)(Ap + (kt+1)*8);
            bv = *(const float4*)(Bp + (kt+1)*8);
        }
        #pragma unroll
        for (int k = 0; k < 8; k++){
            float4 a0 = *(const float4*)&As[cur][k][ty*4];
            float4 a1 = *(const float4*)&As[cur][k][64 + ty*4];
            ull b0 = *(const ull*)&Bs[cur][k][tx*4];
            ull b1 = *(const ull*)&Bs[cur][k][tx*4 + 2];
            ull b2 = *(const ull*)&Bs[cur][k][64 + tx*4];
            ull b3 = *(const ull*)&Bs[cur][k][64 + tx*4 + 2];
            float am[8] = {a0.x,a0.y,a0.z,a0.w,a1.x,a1.y,a1.z,a1.w};
            #pragma unroll
            for (int i = 0; i < 8; i++){
                ull pa = pk2(am[i]);
                fma2(acc[i][0], pa, b0);
                fma2(acc[i][1], pa, b1);
                fma2(acc[i][2], pa, b2);
                fma2(acc[i][3], pa, b3);
            }
        }
        if (kt + 1 < nk){
            int nxt = cur ^ 1;
            As[nxt][acol+0][arow]=av.x; As[nxt][acol+1][arow]=av.y; As[nxt][acol+2][arow]=av.z; As[nxt][acol+3][arow]=av.w;
            Bs[nxt][acol+0][arow]=bv.x; Bs[nxt][acol+1][arow]=bv.y; Bs[nxt][acol+2][arow]=bv.z; Bs[nxt][acol+3][arow]=bv.w;
            __syncthreads();
        }
    }

    int c0 = bx*128 + tx*4;
    float4 bv0 = make_float4(0.f,0.f,0.f,0.f), bv1 = bv0;
    if (bias){ bv0 = *(const float4*)&bias[c0]; bv1 = *(const float4*)&bias[c0+64]; }
    #pragma unroll
    for (int i = 0; i < 8; i++){
        int r = by*128 + ((i < 4) ? (ty*4 + i) : (64 + ty*4 + (i-4)));
        U64F2 u0,u1,u2,u3; u0.u=acc[i][0]; u1.u=acc[i][1]; u2.u=acc[i][2]; u3.u=acc[i][3];
        float4 o0 = make_float4(u0.f.x+bv0.x, u0.f.y+bv0.y, u1.f.x+bv0.z, u1.f.y+bv0.w);
        float4 o1 = make_float4(u2.f.x+bv1.x, u2.f.y+bv1.y, u3.f.x+bv1.z, u3.f.y+bv1.w);
        if (doClip){
            o0.x=fminf(fmaxf(o0.x,-1.f),1.f); o0.y=fminf(fmaxf(o0.y,-1.f),1.f);
            o0.z=fminf(fmaxf(o0.z,-1.f),1.f); o0.w=fminf(fmaxf(o0.w,-1.f),1.f);
            o1.x=fminf(fmaxf(o1.x,-1.f),1.f); o1.y=fminf(fmaxf(o1.y,-1.f),1.f);
            o1.z=fminf(fmaxf(o1.z,-1.f),1.f); o1.w=fminf(fmaxf(o1.w,-1.f),1.f);
        }
        *(float4*)&C[(size_t)r*N + c0] = o0;
        *(float4*)&C[(size_t)r*N + c0 + 64] = o1;
    }
}

// ================= GRU common geometry =========================================
// block = 32 j x 16 b, 256 threads, thread = 1 j x 2 b.
// weights 192KB interleaved + h image 32KB (16 rows x 128 float4, swizzled).

__device__ __forceinline__ void gru_load_weights(const float* whh, float* sm,
                                                 int jbase, int tid){
    const float4* w4 = (const float4*)whh;
    float4* d4 = (float4*)sm;
    for (int idx = tid; idx < 96*128; idx += 256){
        int row = idx >> 7;          // g*32 + jl
        int kq = idx & 127;
        int g = row >> 5, jl = row & 31;
        int dst = ((g*8 + (jl>>2))*128 + kq)*4 + (jl & 3);
        d4[dst] = w4[(size_t)(g*H_ + jbase + jl)*128 + kq];
    }
}

// ---------------- GRU v8: CLUSTER version (16-CTA CGA, DSMEM h exchange) -------
__global__ __launch_bounds__(256) void k_gru_cl(const float* __restrict__ w_hh_f,
                                                const float* __restrict__ w_hh_b,
                                                const float* __restrict__ b_hh_f,
                                                const float* __restrict__ b_hh_b,
                                                float* __restrict__ states){
    extern __shared__ float sm[];
    float4* hs4 = (float4*)(sm + 49152);   // persistent h image (32KB)

    uint32_t rank;
    asm("mov.u32 %0, %%cluster_ctarank;" : "=r"(rank));
    int cid = blockIdx.x >> 4;             // cluster id 0..7
    int dir = cid >> 2;
    int bq  = cid & 3;
    int jbase = (int)rank * 32;
    int bbase = bq * 16;
    const float* whh = dir ? w_hh_b : w_hh_f;
    const float* bhh = dir ? b_hh_b : b_hh_f;
    const float* xg = g_xg[dir];
    int tid = threadIdx.x;
    int jp = tid >> 3;           // 0..31
    int bp = tid & 7;            // 0..7
    int j  = jbase + jp;
    int b0 = bbase + bp*2;
    int bL0 = bp*2, bL1 = bp*2 + 1;
    unsigned key = (unsigned)bp;  // 0..7

    gru_load_weights(whh, sm, jbase, tid);
    // zero h image (t=0 state)
    for (int i = tid; i < 16*128; i += 256) hs4[i] = make_float4(0.f,0.f,0.f,0.f);

    float bhr = bhh[j], bhz = bhh[H_+j], bhn = bhh[2*H_+j];

    __syncthreads();
    asm volatile("barrier.cluster.arrive.aligned;" ::: "memory");
    asm volatile("barrier.cluster.wait.aligned;" ::: "memory");

    const ulonglong2* wu = (const ulonglong2*)sm;
    int wbr = ((0*8 + (jp>>2))*128)*4 + (jp & 3);
    int wbz = ((1*8 + (jp>>2))*128)*4 + (jp & 3);
    int wbn = ((2*8 + (jp>>2))*128)*4 + (jp & 3);
    const ulonglong2* h0row = (const ulonglong2*)(hs4 + bL0*128);
    const ulonglong2* h1row = (const ulonglong2*)(hs4 + bL1*128);

    // DSMEM target byte addresses (own image; mapa redirects per rank)
    int kqj = j >> 2, jo = j & 3;
    uint32_t img = smem_u32(hs4);
    uint32_t my0 = img + ((uint32_t)(bL0*128 + (kqj ^ (int)key)))*16u + (uint32_t)jo*4u;
    uint32_t my1 = img + ((uint32_t)(bL1*128 + (kqj ^ (int)key)))*16u + (uint32_t)jo*4u;
    const float* hq0 = (const float*)(hs4 + bL0*128 + ((unsigned)kqj ^ key));
    const float* hq1 = (const float*)(hs4 + bL1*128 + ((unsigned)kqj ^ key));

    // preload xg for t=0
    int tidx0 = dir ? (S_-1) : 0;
    const float* xA0 = xg + ((size_t)(tidx0*B_ + b0))*H3_;
    const float* xB0 = xA0 + H3_;
    float xr0 = xA0[j], xz0 = xA0[H_+j], xn0 = xA0[2*H_+j];
    float xr1 = xB0[j], xz1 = xB0[H_+j], xn1 = xB0[2*H_+j];

    for (int t = 0; t < S_; t++){
        int tidx = dir ? (S_-1-t) : t;

        // issue next step's xg loads (hidden under the FMA loop)
        float nxr0=0,nxz0=0,nxn0=0,nxr1=0,nxz1=0,nxn1=0;
        if (t + 1 < S_){
            int ntidx = dir ? (S_-2-t) : (t+1);
            const float* nA = xg + ((size_t)(ntidx*B_ + b0))*H3_;
            const float* nB = nA + H3_;
            nxr0 = nA[j]; nxz0 = nA[H_+j]; nxn0 = nA[2*H_+j];
            nxr1 = nB[j]; nxz1 = nB[H_+j]; nxn1 = nB[2*H_+j];
        }

        ull ar0=0,ar1=0,az0=0,az1=0,an0=0,an1=0;
        #pragma unroll 4
        for (int kq = 0; kq < 128; kq++){
            ulonglong2 hA = h0row[kq ^ key];
            ulonglong2 hB = h1row[kq ^ key];
            int k4 = kq << 2;
            ulonglong2 w;
            w = wu[wbr + k4];
            fma2(ar0, hA.x, w.x); fma2(ar0, hA.y, w.y);
            fma2(ar1, hB.x, w.x); fma2(ar1, hB.y, w.y);
            w = wu[wbz + k4];
            fma2(az0, hA.x, w.x); fma2(az0, hA.y, w.y);
            fma2(az1, hB.x, w.x); fma2(az1, hB.y, w.y);
            w = wu[wbn + k4];
            fma2(an0, hA.x, w.x); fma2(an0, hA.y, w.y);
            fma2(an1, hB.x, w.x); fma2(an1, hB.y, w.y);
        }

        float hp0 = hq0[jo];
        float hp1 = hq1[jo];

        // done reading the shared image
        asm volatile("barrier.cluster.arrive.aligned;" ::: "memory");

        U64F2 u;
        u.u=ar0; float sr0=u.f.x+u.f.y;  u.u=ar1; float sr1=u.f.x+u.f.y;
        u.u=az0; float sz0=u.f.x+u.f.y;  u.u=az1; float sz1=u.f.x+u.f.y;
        u.u=an0; float sn0=u.f.x+u.f.y;  u.u=an1; float sn1=u.f.x+u.f.y;

        float r0 = 1.f/(1.f+expf(-(xr0 + sr0 + bhr)));
        float r1 = 1.f/(1.f+expf(-(xr1 + sr1 + bhr)));
        float z0 = 1.f/(1.f+expf(-(xz0 + sz0 + bhz)));
        float z1 = 1.f/(1.f+expf(-(xz1 + sz1 + bhz)));
        float n0 = tanhf(xn0 + r0*(sn0 + bhn));
        float n1 = tanhf(xn1 + r1*(sn1 + bhn));
        float h0 = (1.f-z0)*n0 + z0*hp0;
        float h1 = (1.f-z1)*n1 + z1*hp1;

        states[((size_t)b0*S_ + tidx)*(2*H_) + dir*H_ + j]     = h0;
        states[((size_t)(b0+1)*S_ + tidx)*(2*H_) + dir*H_ + j] = h1;

        // all CTAs finished reading -> safe to overwrite images
        asm volatile("barrier.cluster.wait.aligned;" ::: "memory");

        // broadcast h to all 16 CTA images (incl. own)
        #pragma unroll
        for (int rk = 0; rk < 16; rk++){
            uint32_t r0a, r1a;
            asm volatile("mapa.shared::cluster.u32 %0, %1, %2;" : "=r"(r0a) : "r"(my0), "r"(rk));
            asm volatile("st.shared::cluster.f32 [%0], %1;" :: "r"(r0a), "f"(h0) : "memory");
            asm volatile("mapa.shared::cluster.u32 %0, %1, %2;" : "=r"(r1a) : "r"(my1), "r"(rk));
            asm volatile("st.shared::cluster.f32 [%0], %1;" :: "r"(r1a), "f"(h1) : "memory");
        }

        asm volatile("barrier.cluster.arrive.aligned;" ::: "memory");
        xr0=nxr0; xz0=nxz0; xn0=nxn0; xr1=nxr1; xz1=nxz1; xn1=nxn1;
        asm volatile("barrier.cluster.wait.aligned;" ::: "memory");
    }
}

// ---------------- GRU v6 (proven fallback; global-memory exchange) -------------
__global__ __launch_bounds__(256) void k_gru(const float* __restrict__ w_hh_f,
                                             const float* __restrict__ w_hh_b,
                                             const float* __restrict__ b_hh_f,
                                             const float* __restrict__ b_hh_b,
                                             float* __restrict__ states){
    extern __shared__ float sm[];
    float4* hs4 = (float4*)(sm + 49152);

    int blk = blockIdx.x;
    int dir = blk >> 6;
    int rr = blk & 63;
    int jc = rr >> 2, bq = rr & 3;
    int jbase = jc * 32;
    int bbase = bq * 16;
    int grp = dir*4 + bq;
    const float* whh = dir ? w_hh_b : w_hh_f;
    const float* bhh = dir ? b_hh_b : b_hh_f;
    const float* xg = g_xg[dir];
    int tid = threadIdx.x;
    int jp = tid >> 3;
    int bp = tid & 7;
    int j  = jbase + jp;
    int b0 = bbase + bp*2;
    int bL0 = bp*2, bL1 = bp*2 + 1;
    unsigned key = (unsigned)bp;

    gru_load_weights(whh, sm, jbase, tid);

    float bhr = bhh[j], bhz = bhh[H_+j], bhn = bhh[2*H_+j];

    g_h2[dir][0][(size_t)b0*H_ + j]     = 0.f;
    g_h2[dir][0][(size_t)(b0+1)*H_ + j] = 0.f;
    gbar_grp(grp);

    const ulonglong2* wu = (const ulonglong2*)sm;
    int wbr = ((0*8 + (jp>>2))*128)*4 + (jp & 3);
    int wbz = ((1*8 + (jp>>2))*128)*4 + (jp & 3);
    int wbn = ((2*8 + (jp>>2))*128)*4 + (jp & 3);
    const ulonglong2* h0row = (const ulonglong2*)(hs4 + bL0*128);
    const ulonglong2* h1row = (const ulonglong2*)(hs4 + bL1*128);

    int tidx0 = dir ? (S_-1) : 0;
    const float* xA0 = xg + ((size_t)(tidx0*B_ + b0))*H3_;
    const float* xB0 = xA0 + H3_;
    float xr0 = xA0[j], xz0 = xA0[H_+j], xn0 = xA0[2*H_+j];
    float xr1 = xB0[j], xz1 = xB0[H_+j], xn1 = xB0[2*H_+j];

    for (int t = 0; t < S_; t++){
        int tidx = dir ? (S_-1-t) : t;

        const float4* hr4 = (const float4*)(g_h2[dir][t & 1] + (size_t)bbase*H_);
        #pragma unroll
        for (int i = 0; i < 8; i++){
            int gi = tid + (i << 8);
            int bb = gi >> 7, kq = gi & 127;
            hs4[bb*128 + (kq ^ ((unsigned)(bb >> 1) & 7u))] = hr4[gi];
        }
        __syncthreads();

        float nxr0=0,nxz0=0,nxn0=0,nxr1=0,nxz1=0,nxn1=0;
        if (t + 1 < S_){
            int ntidx = dir ? (S_-2-t) : (t+1);
            const float* nA = xg + ((size_t)(ntidx*B_ + b0))*H3_;
            const float* nB = nA + H3_;
            nxr0 = nA[j]; nxz0 = nA[H_+j]; nxn0 = nA[2*H_+j];
            nxr1 = nB[j]; nxz1 = nB[H_+j]; nxn1 = nB[2*H_+j];
        }

        ull ar0=0,ar1=0,az0=0,az1=0,an0=0,an1=0;
        #pragma unroll 4
        for (int kq = 0; kq < 128; kq++){
            ulonglong2 hA = h0row[kq ^ key];
            ulonglong2 hB = h1row[kq ^ key];
            int k4 = kq << 2;
            ulonglong2 w;
            w = wu[wbr + k4];
            fma2(ar0, hA.x, w.x); fma2(ar0, hA.y, w.y);
            fma2(ar1, hB.x, w.x); fma2(ar1, hB.y, w.y);
            w = wu[wbz + k4];
            fma2(az0, hA.x, w.x); fma2(az0, hA.y, w.y);
            fma2(az1, hB.x, w.x); fma2(az1, hB.y, w.y);
            w = wu[wbn + k4];
            fma2(an0, hA.x, w.x); fma2(an0, hA.y, w.y);
            fma2(an1, hB.x, w.x); fma2(an1, hB.y, w.y);
        }

        int kqj = j >> 2, jo = j & 3;
        float hp0 = ((const float*)(hs4 + bL0*128 + ((unsigned)kqj ^ key)))[jo];
        float hp1 = ((const float*)(hs4 + bL1*128 + ((unsigned)kqj ^ key)))[jo];

        U64F2 u;
        u.u=ar0; float sr0=u.f.x+u.f.y;  u.u=ar1; float sr1=u.f.x+u.f.y;
        u.u=az0; float sz0=u.f.x+u.f.y;  u.u=az1; float sz1=u.f.x+u.f.y;
        u.u=an0; float sn0=u.f.x+u.f.y;  u.u=an1; float sn1=u.f.x+u.f.y;

        float r0 = 1.f/(1.f+expf(-(xr0 + sr0 + bhr)));
        float r1 = 1.f/(1.f+expf(-(xr1 + sr1 + bhr)));
        float z0 = 1.f/(1.f+expf(-(xz0 + sz0 + bhz)));
        float z1 = 1.f/(1.f+expf(-(xz1 + sz1 + bhz)));
        float n0 = tanhf(xn0 + r0*(sn0 + bhn));
        float n1 = tanhf(xn1 + r1*(sn1 + bhn));
        float h0 = (1.f-z0)*n0 + z0*hp0;
        float h1 = (1.f-z1)*n1 + z1*hp1;

        float* hw = g_h2[dir][(t & 1) ^ 1];
        hw[(size_t)b0*H_ + j]     = h0;
        hw[(size_t)(b0+1)*H_ + j] = h1;
        states[((size_t)b0*S_ + tidx)*(2*H_) + dir*H_ + j]     = h0;
        states[((size_t)(b0+1)*S_ + tidx)*(2*H_) + dir*H_ + j] = h1;

        gbar_grp(grp);

        xr0=nxr0; xz0=nxz0; xn0=nxn0; xr1=nxr1; xz1=nxz1; xn1=nxn1;
    }
}

// ---------------- alpha = m1 @ att_w2^T, softmax over S -----------------------
__global__ __launch_bounds__(256) void k_alpha(const float* __restrict__ att_w2,
                                               float* __restrict__ alpha_out){
    __shared__ float w2s[NH_*A_];
    __shared__ float al[NH_*S_];
    int b = blockIdx.x, tid = threadIdx.x;
    for (int i = tid; i < NH_*A_; i += 256) w2s[i] = att_w2[i];
    __syncthreads();
    int s = tid >> 2, h = tid & 3;
    const float* m1r = g_m1 + ((size_t)(b*S_ + s))*A_;
    float acc = 0.f;
    #pragma unroll 4
    for (int k = 0; k < A_; k++) acc += m1r[k]*w2s[h*A_+k];
    al[h*S_+s] = acc;
    __syncthreads();
    int wid = tid >> 5, lane = tid & 31;
    if (wid < NH_){
        float v0 = al[wid*S_+lane], v1 = al[wid*S_+lane+32];
        float mx = fmaxf(v0, v1);
        #pragma unroll
        for (int o = 16; o > 0; o >>= 1) mx = fmaxf(mx, __shfl_xor_sync(0xffffffffu, mx, o));
        float e0 = expf(v0-mx), e1 = expf(v1-mx);
        float sm = e0 + e1;
        #pragma unroll
        for (int o = 16; o > 0; o >>= 1) sm += __shfl_xor_sync(0xffffffffu, sm, o);
        float inv = 1.f/sm;
        alpha_out[(b*NH_+wid)*S_ + lane]      = e0*inv;
        alpha_out[(b*NH_+wid)*S_ + lane + 32] = e1*inv;
    }
}

// ---------------- context = alpha @ states ------------------------------------
__global__ __launch_bounds__(512) void k_context(const float* __restrict__ states,
                                                 const float* __restrict__ alpha_in,
                                                 float* __restrict__ context){
    __shared__ float als[NH_*S_];
    int b = blockIdx.x, tid = threadIdx.x;
    if (tid < NH_*S_) als[tid] = alpha_in[b*NH_*S_ + tid];
    __syncthreads();
    float a0[NH_], a1[NH_];
    #pragma unroll
    for (int h = 0; h < NH_; h++){ a0[h] = 0.f; a1[h] = 0.f; }
    const float* st = states + (size_t)b*S_*2*H_;
    for (int s = 0; s < S_; s++){
        float v0 = st[s*2*H_ + tid];
        float v1 = st[s*2*H_ + H_ + tid];
        #pragma unroll
        for (int h = 0; h < NH_; h++){
            float a = als[h*S_+s];
            a0[h] += a*v0; a1[h] += a*v1;
        }
    }
    float* cb = context + (size_t)b*NH_*2*H_;
    #pragma unroll
    for (int h = 0; h < NH_; h++){
        cb[h*2*H_ + tid]      = a0[h];
        cb[h*2*H_ + H_ + tid] = a1[h];
    }
}

// ---------------- final linear + softmax --------------------------------------
__global__ __launch_bounds__(512) void k_final(const float* __restrict__ context,
                                               const float* __restrict__ lin_w,
                                               const float* __restrict__ lin_b,
                                               float* __restrict__ out){
    __shared__ float red[OUT_];
    int b = blockIdx.x, tid = threadIdx.x, w = tid >> 5, lane = tid & 31;
    const float* cx = context + (size_t)b*4096;
    const float* lw = lin_w + (size_t)w*4096;
    float acc = 0.f;
    for (int k = lane; k < 4096; k += 32) acc += cx[k]*lw[k];
    #pragma unroll
    for (int o = 16; o > 0; o >>= 1) acc += __shfl_xor_sync(0xffffffffu, acc, o);
    if (lane == 0) red[w] = acc + lin_b[w];
    __syncthreads();
    if (tid < 32){
        float v = (lane < OUT_) ? red[lane] : -1e30f;
        float mx = v;
        #pragma unroll
        for (int o = 16; o > 0; o >>= 1) mx = fmaxf(mx, __shfl_xor_sync(0xffffffffu, mx, o));
        float e = (lane < OUT_) ? expf(v - mx) : 0.f;
        float sm = e;
        #pragma unroll
        for (int o = 16; o > 0; o >>= 1) sm += __shfl_xor_sync(0xffffffffu, sm, o);
        if (lane < OUT_) out[b*OUT_ + lane] = e/sm;
    }
}

// ---------------- launch ------------------------------------------------------
extern "C" void kernel_launch(void* const* d_in, const int* in_sizes, int n_in,
                              void* d_out, int out_size){
    const float* inputs  = (const float*)d_in[0];
    const float* conv_w  = (const float*)d_in[2];
    const float* conv_b  = (const float*)d_in[3];
    const float* w_embed = (const float*)d_in[4];
    const float* w_ih_f  = (const float*)d_in[5];
    const float* w_hh_f  = (const float*)d_in[6];
    const float* b_ih_f  = (const float*)d_in[7];
    const float* b_hh_f  = (const float*)d_in[8];
    const float* w_ih_b  = (const float*)d_in[9];
    const float* w_hh_b  = (const float*)d_in[10];
    const float* b_ih_b  = (const float*)d_in[11];
    const float* b_hh_b  = (const float*)d_in[12];
    const float* att_w1  = (const float*)d_in[13];
    const float* att_w2  = (const float*)d_in[14];
    const float* lin_w   = (const float*)d_in[15];
    const float* lin_b   = (const float*)d_in[16];

    float* out     = (float*)d_out;
    float* states  = out + STATES_OFF;
    float* context = out + CONTEXT_OFF;
    float* alpha   = out + ALPHA_OFF;

    void *p_vec, *p_emb, *p_xg, *p_m1;
    cudaGetSymbolAddress(&p_vec, g_vec);
    cudaGetSymbolAddress(&p_emb, g_emb);
    cudaGetSymbolAddress(&p_xg,  g_xg);
    cudaGetSymbolAddress(&p_m1,  g_m1);
    float* vec = (float*)p_vec;
    float* emb = (float*)p_emb;
    float* xg0 = (float*)p_xg;
    float* m1  = (float*)p_m1;

    const int conv_smem = P_*D_*4;                     // 65536
    const int gru_smem  = 49152*4 + 16*128*16;         // 192KB + 32KB = 229376
    cudaFuncSetAttribute(k_conv_vec, cudaFuncAttributeMaxDynamicSharedMemorySize, conv_smem);
    cudaFuncSetAttribute(k_gru,      cudaFuncAttributeMaxDynamicSharedMemorySize, gru_smem);
    cudaFuncSetAttribute(k_gru_cl,   cudaFuncAttributeMaxDynamicSharedMemorySize, gru_smem);
    cudaFuncSetAttribute(k_gru_cl,   cudaFuncAttributeNonPortableClusterSizeAllowed, 1);

    // 1) conv + weighted-sum (inputs read once)
    k_conv_vec<<<BS_, 256, conv_smem>>>(inputs, conv_w, conv_b);
    // 2) emb = clip(vec @ w_embed^T)
    k_sgemm<<<dim3(E_/128, BS_/128), 256>>>(vec, w_embed, w_embed, emb,
                                            BS_, E_, D_, nullptr, nullptr, 1, 0);
    // 3) xg = emb([S,B] permuted) @ w_ih^T + b_ih, BOTH directions in one launch
    k_sgemm<<<dim3(H3_/128, BS_/128, 2), 256>>>(emb, w_ih_f, w_ih_b, xg0,
                                                BS_, H3_, E_, b_ih_f, b_ih_b, 0, 1);
    // 4) persistent bidirectional GRU -> states
    {
        cudaLaunchConfig_t cfg = {};
        cfg.gridDim = dim3(128, 1, 1);
        cfg.blockDim = dim3(256, 1, 1);
        cfg.dynamicSmemBytes = gru_smem;
        cfg.stream = 0;
        cudaLaunchAttribute at[1];
        at[0].id = cudaLaunchAttributeClusterDimension;
        at[0].val.clusterDim.x = 16; at[0].val.clusterDim.y = 1; at[0].val.clusterDim.z = 1;
        cfg.attrs = at;
        cfg.numAttrs = 1;
        int nclus = 0;
        cudaError_t qe = cudaOccupancyMaxActiveClusters(&nclus, (void*)k_gru_cl, &cfg);
        if (qe == cudaSuccess && nclus >= 8){
            cudaLaunchKernelEx(&cfg, k_gru_cl, w_hh_f, w_hh_b, b_hh_f, b_hh_b, states);
        } else {
            cudaGetLastError();   // clear any query error
            k_gru<<<128, 256, gru_smem>>>(w_hh_f, w_hh_b, b_hh_f, b_hh_b, states);
        }
    }
    // 5) m1 = clip(states @ att_w1^T)
    k_sgemm<<<dim3(A_/128, BS_/128), 256>>>(states, att_w1, att_w1, m1,
                                            BS_, A_, 2*H_, nullptr, nullptr, 1, 0);
    // 6) alpha = softmax_S(m1 @ att_w2^T), transposed to [B,NH,S]
    k_alpha<<<B_, 256>>>(att_w2, alpha);
    // 7) context
    k_context<<<B_, 512>>>(states, alpha, context);
    // 8) out = softmax(context @ lin_w^T + lin_b)
    k_final<<<B_, 512>>>(context, lin_w, lin_b, out);
}

// round 10
// speedup vs baseline: 1.0653x; 1.0653x over previous
#include <cuda_runtime.h>
#include <cstdint>
#include <cstdio>

#define B_ 64
#define S_ 64
#define P_ 32
#define D_ 512
#define E_ 512
#define H_ 512
#define H3_ 1536
#define A_ 256
#define NH_ 4
#define OUT_ 16
#define BS_ (B_*S_)

// d_out layout: out[64,16] | states[B,S,2H] | context[B,4096] | alpha_actv[B,NH,S]
#define STATES_OFF 1024
#define CONTEXT_OFF (1024 + BS_*2*H_)
#define ALPHA_OFF (CONTEXT_OFF + B_*NH_*2*H_)

// ---------------- scratch (device globals; no allocation allowed) -------------
__device__ float g_vec[BS_*D_];
__device__ float g_emb[BS_*E_];
__device__ float g_xg[2][BS_*H3_];
__device__ float g_h2[2][2][B_*H_];     // [dir][buf][b*H+j]
__device__ float g_m1[BS_*A_];
__device__ unsigned g_cnt8[8][32];      // 8 barrier groups, padded
__device__ unsigned g_gen8[8][32];

typedef unsigned long long ull;

// ---------------- f32x2 helpers (FFMA2: 2x fp32 FMA throughput) ---------------
__device__ __forceinline__ ull pk2(float x){
    ull r;
    asm("mov.b64 %0, {%1, %1};" : "=l"(r) : "f"(x));
    return r;
}
__device__ __forceinline__ void fma2(ull& d, ull a, ull b){
    asm("fma.rn.f32x2 %0, %1, %2, %0;" : "+l"(d) : "l"(a), "l"(b));
}
union U64F2 { ull u; float2 f; };

// ---------------- simple group grid barrier (16 blocks per group, R6-proven) --
__device__ __forceinline__ void gbar_grp(int grp){
    __syncthreads();
    if (threadIdx.x == 0){
        __threadfence();
        unsigned g = *((volatile unsigned*)&g_gen8[grp][0]);
        if (atomicAdd(&g_cnt8[grp][0], 1u) == 15u){
            g_cnt8[grp][0] = 0u;
            __threadfence();
            atomicExch(&g_gen8[grp][0], g + 1u);
        } else {
            while (*((volatile unsigned*)&g_gen8[grp][0]) == g) { }
        }
        __threadfence();
    }
    __syncthreads();
}

// ---------------- fused conv + weighted-sum (reads inputs ONCE) ---------------
__global__ __launch_bounds__(256) void k_conv_vec(const float* __restrict__ inp,
                                                  const float* __restrict__ conv_w,
                                                  const float* __restrict__ conv_b){
    extern __shared__ float tile[];          // P_*D_ = 16384 floats = 64KB
    __shared__ float cw[D_];
    __shared__ float convp[P_];
    int bs = blockIdx.x;
    int tid = threadIdx.x;
    const float4* src4 = (const float4*)(inp + (size_t)bs*P_*D_);
    float4* t4 = (float4*)tile;
    for (int i = tid; i < D_; i += 256) cw[i] = conv_w[i];
    for (int i = tid; i < P_*D_/4; i += 256) t4[i] = src4[i];
    __syncthreads();
    int wid = tid >> 5, lane = tid & 31;
    float cb = conv_b[0];
    for (int p = wid; p < P_; p += 8){
        float s = 0.f;
        for (int d = lane; d < D_; d += 32) s += tile[p*D_+d]*cw[d];
        #pragma unroll
        for (int o = 16; o > 0; o >>= 1) s += __shfl_xor_sync(0xffffffffu, s, o);
        if (lane == 0) convp[p] = s + cb;
    }
    __syncthreads();
    for (int d = tid; d < D_; d += 256){
        float acc = 0.f;
        #pragma unroll
        for (int p = 0; p < P_; p++) acc += convp[p]*tile[p*D_+d];
        g_vec[(size_t)bs*D_ + d] = acc;
    }
}

// ---------------- SGEMM (R6 + B-LDS128 merge): C = A * Bw^T -------------------
// blockIdx.z == 1 -> use Bw2/bias2, write C + M*N (for merged xg_f/xg_b)
__global__ __launch_bounds__(256, 2) void k_sgemm(const float* __restrict__ A,
                                                  const float* __restrict__ Bw,
                                                  const float* __restrict__ Bw2,
                                                  float* __restrict__ C,
                                                  int M, int N, int K,
                                                  const float* __restrict__ bias,
                                                  const float* __restrict__ bias2,
                                                  int doClip, int permA){
    __shared__ float As[2][8][128];
    __shared__ float Bs[2][8][128];
    int tid = threadIdx.x;
    int bx = blockIdx.x, by = blockIdx.y;
    if (blockIdx.z){ Bw = Bw2; bias = bias2; C += (size_t)M*N; }
    int arow = tid >> 1;
    int acol = (tid & 1) * 4;
    int orow = by*128 + arow;
    int grow = permA ? ((orow & 63)*64 + (orow >> 6)) : orow;
    const float* Ap = A + (size_t)grow*K + acol;
    const float* Bp = Bw + (size_t)(bx*128 + arow)*K + acol;

    float4 av = *(const float4*)Ap;
    float4 bv = *(const float4*)Bp;
    As[0][acol+0][arow]=av.x; As[0][acol+1][arow]=av.y; As[0][acol+2][arow]=av.z; As[0][acol+3][arow]=av.w;
    Bs[0][acol+0][arow]=bv.x; Bs[0][acol+1][arow]=bv.y; Bs[0][acol+2][arow]=bv.z; Bs[0][acol+3][arow]=bv.w;
    __syncthreads();

    int tx = tid & 15, ty = tid >> 4;
    ull acc[8][4];
    #pragma unroll
    for (int i = 0; i < 8; i++){
        #pragma unroll
        for (int j = 0; j < 4; j++) acc[i][j] = 0ULL;
    }

    int nk = K >> 3;
    for (int kt = 0; kt < nk; kt++){
        int cur = kt & 1;
        if (kt + 1 < nk){
            av = *(const float4*)(Ap + (kt+1)*8);
            bv = *(const float4*)(Bp + (kt+1)*8);
        }
        #pragma unroll
        for (int k = 0; k < 8; k++){
            float4 a0 = *(const float4*)&As[cur][k][ty*4];
            float4 a1 = *(const float4*)&As[cur][k][64 + ty*4];
            ulonglong2 B0 = *(const ulonglong2*)&Bs[cur][k][tx*4];        // b0,b1
            ulonglong2 B1 = *(const ulonglong2*)&Bs[cur][k][64 + tx*4];   // b2,b3
            float am[8] = {a0.x,a0.y,a0.z,a0.w,a1.x,a1.y,a1.z,a1.w};
            #pragma unroll
            for (int i = 0; i < 8; i++){
                ull pa = pk2(am[i]);
                fma2(acc[i][0], pa, B0.x);
                fma2(acc[i][1], pa, B0.y);
                fma2(acc[i][2], pa, B1.x);
                fma2(acc[i][3], pa, B1.y);
            }
        }
        if (kt + 1 < nk){
            int nxt = cur ^ 1;
            As[nxt][acol+0][arow]=av.x; As[nxt][acol+1][arow]=av.y; As[nxt][acol+2][arow]=av.z; As[nxt][acol+3][arow]=av.w;
            Bs[nxt][acol+0][arow]=bv.x; Bs[nxt][acol+1][arow]=bv.y; Bs[nxt][acol+2][arow]=bv.z; Bs[nxt][acol+3][arow]=bv.w;
            __syncthreads();
        }
    }

    int c0 = bx*128 + tx*4;
    float4 bv0 = make_float4(0.f,0.f,0.f,0.f), bv1 = bv0;
    if (bias){ bv0 = *(const float4*)&bias[c0]; bv1 = *(const float4*)&bias[c0+64]; }
    #pragma unroll
    for (int i = 0; i < 8; i++){
        int r = by*128 + ((i < 4) ? (ty*4 + i) : (64 + ty*4 + (i-4)));
        U64F2 u0,u1,u2,u3; u0.u=acc[i][0]; u1.u=acc[i][1]; u2.u=acc[i][2]; u3.u=acc[i][3];
        float4 o0 = make_float4(u0.f.x+bv0.x, u0.f.y+bv0.y, u1.f.x+bv0.z, u1.f.y+bv0.w);
        float4 o1 = make_float4(u2.f.x+bv1.x, u2.f.y+bv1.y, u3.f.x+bv1.z, u3.f.y+bv1.w);
        if (doClip){
            o0.x=fminf(fmaxf(o0.x,-1.f),1.f); o0.y=fminf(fmaxf(o0.y,-1.f),1.f);
            o0.z=fminf(fmaxf(o0.z,-1.f),1.f); o0.w=fminf(fmaxf(o0.w,-1.f),1.f);
            o1.x=fminf(fmaxf(o1.x,-1.f),1.f); o1.y=fminf(fmaxf(o1.y,-1.f),1.f);
            o1.z=fminf(fmaxf(o1.z,-1.f),1.f); o1.w=fminf(fmaxf(o1.w,-1.f),1.f);
        }
        *(float4*)&C[(size_t)r*N + c0] = o0;
        *(float4*)&C[(size_t)r*N + c0 + 64] = o1;
    }
}

// ---------------- persistent bidirectional GRU (R6-proven, verbatim) ----------
// 128 blocks x 256 thr (1 CTA/SM). block = (dir, jc 0..15, bq 0..3) -> 32j x 16b.
// thread = 1j x 2b. weights 192KB (4-row interleave) + h image 32KB = 224KB.
// 8 barrier groups (dir,bq) of 16 blocks.
__global__ __launch_bounds__(256) void k_gru(const float* __restrict__ w_hh_f,
                                             const float* __restrict__ w_hh_b,
                                             const float* __restrict__ b_hh_f,
                                             const float* __restrict__ b_hh_b,
                                             float* __restrict__ states){
    extern __shared__ float sm[];
    float4* hs4 = (float4*)(sm + 49152);   // h image: 16 rows x 128 float4 (32KB)

    int blk = blockIdx.x;        // 128
    int dir = blk >> 6;
    int rr = blk & 63;
    int jc = rr >> 2, bq = rr & 3;
    int jbase = jc * 32;
    int bbase = bq * 16;
    int grp = dir*4 + bq;        // 0..7
    const float* whh = dir ? w_hh_b : w_hh_f;
    const float* bhh = dir ? b_hh_b : b_hh_f;
    const float* xg = g_xg[dir];
    int tid = threadIdx.x;
    int jp = tid >> 3;           // 0..31
    int bp = tid & 7;            // 0..7
    int j  = jbase + jp;
    int b0 = bbase + bp*2;
    int bL0 = bp*2, bL1 = bp*2 + 1;
    unsigned key = (unsigned)bp;  // 0..7

    // weights: 96 rows (g*32 + jl). float4 dst = ((g*8 + (jl>>2))*128 + kq)*4 + (jl&3)
    {
        const float4* w4 = (const float4*)whh;
        float4* d4 = (float4*)sm;
        for (int idx = tid; idx < 96*128; idx += 256){
            int row = idx >> 7;          // g*32 + jl
            int kq = idx & 127;
            int g = row >> 5, jl = row & 31;
            int dst = ((g*8 + (jl>>2))*128 + kq)*4 + (jl & 3);
            d4[dst] = w4[(size_t)(g*H_ + jbase + jl)*128 + kq];
        }
    }

    float bhr = bhh[j], bhz = bhh[H_+j], bhn = bhh[2*H_+j];

    g_h2[dir][0][(size_t)b0*H_ + j]     = 0.f;
    g_h2[dir][0][(size_t)(b0+1)*H_ + j] = 0.f;
    gbar_grp(grp);

    const ulonglong2* wu = (const ulonglong2*)sm;
    int wbr = ((0*8 + (jp>>2))*128)*4 + (jp & 3);
    int wbz = ((1*8 + (jp>>2))*128)*4 + (jp & 3);
    int wbn = ((2*8 + (jp>>2))*128)*4 + (jp & 3);
    const ulonglong2* h0row = (const ulonglong2*)(hs4 + bL0*128);
    const ulonglong2* h1row = (const ulonglong2*)(hs4 + bL1*128);

    // preload xg for t=0
    int tidx0 = dir ? (S_-1) : 0;
    const float* xA0 = xg + ((size_t)(tidx0*B_ + b0))*H3_;
    const float* xB0 = xA0 + H3_;
    float xr0 = xA0[j], xz0 = xA0[H_+j], xn0 = xA0[2*H_+j];
    float xr1 = xB0[j], xz1 = xB0[H_+j], xn1 = xB0[2*H_+j];

    for (int t = 0; t < S_; t++){
        int tidx = dir ? (S_-1-t) : t;

        // stage this group's 16 h rows (32KB), coalesced LDG -> swizzled STS
        const float4* hr4 = (const float4*)(g_h2[dir][t & 1] + (size_t)bbase*H_);
        #pragma unroll
        for (int i = 0; i < 8; i++){
            int gi = tid + (i << 8);
            int bb = gi >> 7, kq = gi & 127;
            hs4[bb*128 + (kq ^ ((unsigned)(bb >> 1) & 7u))] = hr4[gi];
        }
        __syncthreads();

        // issue next step's xg loads (hidden under the FMA loop)
        float nxr0=0,nxz0=0,nxn0=0,nxr1=0,nxz1=0,nxn1=0;
        if (t + 1 < S_){
            int ntidx = dir ? (S_-2-t) : (t+1);
            const float* nA = xg + ((size_t)(ntidx*B_ + b0))*H3_;
            const float* nB = nA + H3_;
            nxr0 = nA[j]; nxz0 = nA[H_+j]; nxn0 = nA[2*H_+j];
            nxr1 = nB[j]; nxz1 = nB[H_+j]; nxn1 = nB[2*H_+j];
        }

        ull ar0=0,ar1=0,az0=0,az1=0,an0=0,an1=0;
        #pragma unroll 4
        for (int kq = 0; kq < 128; kq++){
            ulonglong2 hA = h0row[kq ^ key];
            ulonglong2 hB = h1row[kq ^ key];
            int k4 = kq << 2;
            ulonglong2 w;
            w = wu[wbr + k4];
            fma2(ar0, hA.x, w.x); fma2(ar0, hA.y, w.y);
            fma2(ar1, hB.x, w.x); fma2(ar1, hB.y, w.y);
            w = wu[wbz + k4];
            fma2(az0, hA.x, w.x); fma2(az0, hA.y, w.y);
            fma2(az1, hB.x, w.x); fma2(az1, hB.y, w.y);
            w = wu[wbn + k4];
            fma2(an0, hA.x, w.x); fma2(an0, hA.y, w.y);
            fma2(an1, hB.x, w.x); fma2(an1, hB.y, w.y);
        }

        int kqj = j >> 2, jo = j & 3;
        float hp0 = ((const float*)(hs4 + bL0*128 + ((unsigned)kqj ^ key)))[jo];
        float hp1 = ((const float*)(hs4 + bL1*128 + ((unsigned)kqj ^ key)))[jo];

        U64F2 u;
        u.u=ar0; float sr0=u.f.x+u.f.y;  u.u=ar1; float sr1=u.f.x+u.f.y;
        u.u=az0; float sz0=u.f.x+u.f.y;  u.u=az1; float sz1=u.f.x+u.f.y;
        u.u=an0; float sn0=u.f.x+u.f.y;  u.u=an1; float sn1=u.f.x+u.f.y;

        float r0 = 1.f/(1.f+expf(-(xr0 + sr0 + bhr)));
        float r1 = 1.f/(1.f+expf(-(xr1 + sr1 + bhr)));
        float z0 = 1.f/(1.f+expf(-(xz0 + sz0 + bhz)));
        float z1 = 1.f/(1.f+expf(-(xz1 + sz1 + bhz)));
        float n0 = tanhf(xn0 + r0*(sn0 + bhn));
        float n1 = tanhf(xn1 + r1*(sn1 + bhn));
        float h0 = (1.f-z0)*n0 + z0*hp0;
        float h1 = (1.f-z1)*n1 + z1*hp1;

        float* hw = g_h2[dir][(t & 1) ^ 1];
        hw[(size_t)b0*H_ + j]     = h0;
        hw[(size_t)(b0+1)*H_ + j] = h1;
        states[((size_t)b0*S_ + tidx)*(2*H_) + dir*H_ + j]     = h0;
        states[((size_t)(b0+1)*S_ + tidx)*(2*H_) + dir*H_ + j] = h1;

        gbar_grp(grp);

        xr0=nxr0; xz0=nxz0; xn0=nxn0; xr1=nxr1; xz1=nxz1; xn1=nxn1;
    }
}

// ---------------- alpha = m1 @ att_w2^T, softmax over S -----------------------
__global__ __launch_bounds__(256) void k_alpha(const float* __restrict__ att_w2,
                                               float* __restrict__ alpha_out){
    __shared__ float w2s[NH_*A_];
    __shared__ float al[NH_*S_];
    int b = blockIdx.x, tid = threadIdx.x;
    for (int i = tid; i < NH_*A_; i += 256) w2s[i] = att_w2[i];
    __syncthreads();
    int s = tid >> 2, h = tid & 3;
    const float* m1r = g_m1 + ((size_t)(b*S_ + s))*A_;
    float acc = 0.f;
    #pragma unroll 4
    for (int k = 0; k < A_; k++) acc += m1r[k]*w2s[h*A_+k];
    al[h*S_+s] = acc;
    __syncthreads();
    int wid = tid >> 5, lane = tid & 31;
    if (wid < NH_){
        float v0 = al[wid*S_+lane], v1 = al[wid*S_+lane+32];
        float mx = fmaxf(v0, v1);
        #pragma unroll
        for (int o = 16; o > 0; o >>= 1) mx = fmaxf(mx, __shfl_xor_sync(0xffffffffu, mx, o));
        float e0 = expf(v0-mx), e1 = expf(v1-mx);
        float sm = e0 + e1;
        #pragma unroll
        for (int o = 16; o > 0; o >>= 1) sm += __shfl_xor_sync(0xffffffffu, sm, o);
        float inv = 1.f/sm;
        alpha_out[(b*NH_+wid)*S_ + lane]      = e0*inv;
        alpha_out[(b*NH_+wid)*S_ + lane + 32] = e1*inv;
    }
}

// ---------------- context = alpha @ states ------------------------------------
__global__ __launch_bounds__(512) void k_context(const float* __restrict__ states,
                                                 const float* __restrict__ alpha_in,
                                                 float* __restrict__ context){
    __shared__ float als[NH_*S_];
    int b = blockIdx.x, tid = threadIdx.x;
    if (tid < NH_*S_) als[tid] = alpha_in[b*NH_*S_ + tid];
    __syncthreads();
    float a0[NH_], a1[NH_];
    #pragma unroll
    for (int h = 0; h < NH_; h++){ a0[h] = 0.f; a1[h] = 0.f; }
    const float* st = states + (size_t)b*S_*2*H_;
    for (int s = 0; s < S_; s++){
        float v0 = st[s*2*H_ + tid];
        float v1 = st[s*2*H_ + H_ + tid];
        #pragma unroll
        for (int h = 0; h < NH_; h++){
            float a = als[h*S_+s];
            a0[h] += a*v0; a1[h] += a*v1;
        }
    }
    float* cb = context + (size_t)b*NH_*2*H_;
    #pragma unroll
    for (int h = 0; h < NH_; h++){
        cb[h*2*H_ + tid]      = a0[h];
        cb[h*2*H_ + H_ + tid] = a1[h];
    }
}

// ---------------- final linear + softmax --------------------------------------
__global__ __launch_bounds__(512) void k_final(const float* __restrict__ context,
                                               const float* __restrict__ lin_w,
                                               const float* __restrict__ lin_b,
                                               float* __restrict__ out){
    __shared__ float red[OUT_];
    int b = blockIdx.x, tid = threadIdx.x, w = tid >> 5, lane = tid & 31;
    const float* cx = context + (size_t)b*4096;
    const float* lw = lin_w + (size_t)w*4096;
    float acc = 0.f;
    for (int k = lane; k < 4096; k += 32) acc += cx[k]*lw[k];
    #pragma unroll
    for (int o = 16; o > 0; o >>= 1) acc += __shfl_xor_sync(0xffffffffu, acc, o);
    if (lane == 0) red[w] = acc + lin_b[w];
    __syncthreads();
    if (tid < 32){
        float v = (lane < OUT_) ? red[lane] : -1e30f;
        float mx = v;
        #pragma unroll
        for (int o = 16; o > 0; o >>= 1) mx = fmaxf(mx, __shfl_xor_sync(0xffffffffu, mx, o));
        float e = (lane < OUT_) ? expf(v - mx) : 0.f;
        float sm = e;
        #pragma unroll
        for (int o = 16; o > 0; o >>= 1) sm += __shfl_xor_sync(0xffffffffu, sm, o);
        if (lane < OUT_) out[b*OUT_ + lane] = e/sm;
    }
}

// ---------------- launch ------------------------------------------------------
extern "C" void kernel_launch(void* const* d_in, const int* in_sizes, int n_in,
                              void* d_out, int out_size){
    const float* inputs  = (const float*)d_in[0];
    const float* conv_w  = (const float*)d_in[2];
    const float* conv_b  = (const float*)d_in[3];
    const float* w_embed = (const float*)d_in[4];
    const float* w_ih_f  = (const float*)d_in[5];
    const float* w_hh_f  = (const float*)d_in[6];
    const float* b_ih_f  = (const float*)d_in[7];
    const float* b_hh_f  = (const float*)d_in[8];
    const float* w_ih_b  = (const float*)d_in[9];
    const float* w_hh_b  = (const float*)d_in[10];
    const float* b_ih_b  = (const float*)d_in[11];
    const float* b_hh_b  = (const float*)d_in[12];
    const float* att_w1  = (const float*)d_in[13];
    const float* att_w2  = (const float*)d_in[14];
    const float* lin_w   = (const float*)d_in[15];
    const float* lin_b   = (const float*)d_in[16];

    float* out     = (float*)d_out;
    float* states  = out + STATES_OFF;
    float* context = out + CONTEXT_OFF;
    float* alpha   = out + ALPHA_OFF;

    void *p_vec, *p_emb, *p_xg, *p_m1;
    cudaGetSymbolAddress(&p_vec, g_vec);
    cudaGetSymbolAddress(&p_emb, g_emb);
    cudaGetSymbolAddress(&p_xg,  g_xg);
    cudaGetSymbolAddress(&p_m1,  g_m1);
    float* vec = (float*)p_vec;
    float* emb = (float*)p_emb;
    float* xg0 = (float*)p_xg;
    float* m1  = (float*)p_m1;

    const int conv_smem = P_*D_*4;                     // 65536
    const int gru_smem  = 49152*4 + 16*128*16;         // 192KB + 32KB = 229376
    cudaFuncSetAttribute(k_conv_vec, cudaFuncAttributeMaxDynamicSharedMemorySize, conv_smem);
    cudaFuncSetAttribute(k_gru,      cudaFuncAttributeMaxDynamicSharedMemorySize, gru_smem);

    // 1) conv + weighted-sum (inputs read once)
    k_conv_vec<<<BS_, 256, conv_smem>>>(inputs, conv_w, conv_b);
    // 2) emb = clip(vec @ w_embed^T)
    k_sgemm<<<dim3(E_/128, BS_/128), 256>>>(vec, w_embed, w_embed, emb,
                                            BS_, E_, D_, nullptr, nullptr, 1, 0);
    // 3) xg = emb([S,B] permuted) @ w_ih^T + b_ih, BOTH directions in one launch
    k_sgemm<<<dim3(H3_/128, BS_/128, 2), 256>>>(emb, w_ih_f, w_ih_b, xg0,
                                                BS_, H3_, E_, b_ih_f, b_ih_b, 0, 1);
    // 4) persistent bidirectional GRU -> states (written straight into d_out)
    k_gru<<<128, 256, gru_smem>>>(w_hh_f, w_hh_b, b_hh_f, b_hh_b, states);
    // 5) m1 = clip(states @ att_w1^T)
    k_sgemm<<<dim3(A_/128, BS_/128), 256>>>(states, att_w1, att_w1, m1,
                                            BS_, A_, 2*H_, nullptr, nullptr, 1, 0);
    // 6) alpha = softmax_S(m1 @ att_w2^T), transposed to [B,NH,S]
    k_alpha<<<B_, 256>>>(att_w2, alpha);
    // 7) context
    k_context<<<B_, 512>>>(states, alpha, context);
    // 8) out = softmax(context @ lin_w^T + lin_b)
    k_final<<<B_, 512>>>(context, lin_w, lin_b, out);
}

// round 11
// speedup vs baseline: 1.1467x; 1.0764x over previous
#include <cuda_runtime.h>
#include <cuda_bf16.h>
#include <cstdint>
#include <cstdio>

#define B_ 64
#define S_ 64
#define P_ 32
#define D_ 512
#define E_ 512
#define H_ 512
#define H3_ 1536
#define A_ 256
#define NH_ 4
#define OUT_ 16
#define BS_ (B_*S_)

// d_out layout: out[64,16] | states[B,S,2H] | context[B,4096] | alpha_actv[B,NH,S]
#define STATES_OFF 1024
#define CONTEXT_OFF (1024 + BS_*2*H_)
#define ALPHA_OFF (CONTEXT_OFF + B_*NH_*2*H_)

// ---------------- scratch (device globals; no allocation allowed) -------------
__device__ float g_vec[BS_*D_];
__device__ float g_emb[BS_*E_];
__device__ float g_xg[2][BS_*H3_];
__device__ float g_h2[2][2][B_*H_];     // [dir][buf][b*H+j]
__device__ float g_m1[BS_*A_];
__device__ unsigned g_cnt8[8][32];      // 8 barrier groups, padded
__device__ unsigned g_gen8[8][32];

typedef unsigned long long ull;

// ---------------- f32x2 helpers (FFMA2: 2x fp32 FMA throughput) ---------------
__device__ __forceinline__ ull pk2(float x){
    ull r;
    asm("mov.b64 %0, {%1, %1};" : "=l"(r) : "f"(x));
    return r;
}
__device__ __forceinline__ void fma2(ull& d, ull a, ull b){
    asm("fma.rn.f32x2 %0, %1, %2, %0;" : "+l"(d) : "l"(a), "l"(b));
}
union U64F2 { ull u; float2 f; };

// ---------------- simple group grid barrier (16 blocks per group, R6-proven) --
__device__ __forceinline__ void gbar_grp(int grp){
    __syncthreads();
    if (threadIdx.x == 0){
        __threadfence();
        unsigned g = *((volatile unsigned*)&g_gen8[grp][0]);
        if (atomicAdd(&g_cnt8[grp][0], 1u) == 15u){
            g_cnt8[grp][0] = 0u;
            __threadfence();
            atomicExch(&g_gen8[grp][0], g + 1u);
        } else {
            while (*((volatile unsigned*)&g_gen8[grp][0]) == g) { }
        }
        __threadfence();
    }
    __syncthreads();
}

// ---------------- fused conv + weighted-sum (reads inputs ONCE) ---------------
__global__ __launch_bounds__(256) void k_conv_vec(const float* __restrict__ inp,
                                                  const float* __restrict__ conv_w,
                                                  const float* __restrict__ conv_b){
    extern __shared__ float tile[];          // P_*D_ = 16384 floats = 64KB
    __shared__ float cw[D_];
    __shared__ float convp[P_];
    int bs = blockIdx.x;
    int tid = threadIdx.x;
    const float4* src4 = (const float4*)(inp + (size_t)bs*P_*D_);
    float4* t4 = (float4*)tile;
    for (int i = tid; i < D_; i += 256) cw[i] = conv_w[i];
    for (int i = tid; i < P_*D_/4; i += 256) t4[i] = src4[i];
    __syncthreads();
    int wid = tid >> 5, lane = tid & 31;
    float cb = conv_b[0];
    for (int p = wid; p < P_; p += 8){
        float s = 0.f;
        for (int d = lane; d < D_; d += 32) s += tile[p*D_+d]*cw[d];
        #pragma unroll
        for (int o = 16; o > 0; o >>= 1) s += __shfl_xor_sync(0xffffffffu, s, o);
        if (lane == 0) convp[p] = s + cb;
    }
    __syncthreads();
    for (int d = tid; d < D_; d += 256){
        float acc = 0.f;
        #pragma unroll
        for (int p = 0; p < P_; p++) acc += convp[p]*tile[p*D_+d];
        g_vec[(size_t)bs*D_ + d] = acc;
    }
}

// ---------------- split-bf16 HMMA GEMM: C[M,N] = A[M,K] @ Bw[N,K]^T -----------
// D = Ahi*Bhi + Ahi*Blo + Alo*Bhi (fp32 accum) via mma.sync.m16n8k16.
// Block tile 128x64, 8 warps (4 m x 2 n), warp tile 32x32, K-chunks of 16.
// blockIdx.z==1 -> Bw2/bias2, C += M*N.
__device__ __forceinline__ void bsplit4(float4 v, ull& hi, ull& lo){
    __nv_bfloat16 h0 = __float2bfloat16_rn(v.x);
    __nv_bfloat16 h1 = __float2bfloat16_rn(v.y);
    __nv_bfloat16 h2 = __float2bfloat16_rn(v.z);
    __nv_bfloat16 h3 = __float2bfloat16_rn(v.w);
    __nv_bfloat16 l0 = __float2bfloat16_rn(v.x - __bfloat162float(h0));
    __nv_bfloat16 l1 = __float2bfloat16_rn(v.y - __bfloat162float(h1));
    __nv_bfloat16 l2 = __float2bfloat16_rn(v.z - __bfloat162float(h2));
    __nv_bfloat16 l3 = __float2bfloat16_rn(v.w - __bfloat162float(h3));
    hi = (ull)__bfloat16_as_ushort(h0) | ((ull)__bfloat16_as_ushort(h1) << 16)
       | ((ull)__bfloat16_as_ushort(h2) << 32) | ((ull)__bfloat16_as_ushort(h3) << 48);
    lo = (ull)__bfloat16_as_ushort(l0) | ((ull)__bfloat16_as_ushort(l1) << 16)
       | ((ull)__bfloat16_as_ushort(l2) << 32) | ((ull)__bfloat16_as_ushort(l3) << 48);
}
__device__ __forceinline__ void mma16816(float* c, const unsigned* a, const unsigned* b){
    asm volatile(
        "mma.sync.aligned.m16n8k16.row.col.f32.bf16.bf16.f32 "
        "{%0,%1,%2,%3}, {%4,%5,%6,%7}, {%8,%9}, {%0,%1,%2,%3};"
        : "+f"(c[0]), "+f"(c[1]), "+f"(c[2]), "+f"(c[3])
        : "r"(a[0]), "r"(a[1]), "r"(a[2]), "r"(a[3]), "r"(b[0]), "r"(b[1]));
}

__global__ __launch_bounds__(256) void k_bgemm(const float* __restrict__ A,
                                               const float* __restrict__ Bw,
                                               const float* __restrict__ Bw2,
                                               float* __restrict__ C,
                                               int M, int N, int K,
                                               const float* __restrict__ bias,
                                               const float* __restrict__ bias2,
                                               int doClip, int permA){
    __shared__ __align__(16) unsigned short sAh[2][128*16];  // 8KB
    __shared__ __align__(16) unsigned short sAl[2][128*16];  // 8KB
    __shared__ __align__(16) unsigned short sBh[2][64*16];   // 4KB
    __shared__ __align__(16) unsigned short sBl[2][64*16];   // 4KB

    int tid = threadIdx.x;
    int wid = tid >> 5, lane = tid & 31;
    if (blockIdx.z){ Bw = Bw2; bias = bias2; C += (size_t)M*N; }
    int mbase = blockIdx.y * 128;
    int nbase = blockIdx.x * 64;

    // staging assignment: A rows (2 float4/thread), B rows (1 float4/thread)
    int ia0 = tid*2, ia1 = tid*2 + 1;
    int ra0 = ia0 >> 2, ca0 = (ia0 & 3)*4;
    int ra1 = ia1 >> 2, ca1 = (ia1 & 3)*4;
    int rb  = tid >> 2, cb = (tid & 3)*4;
    int ga0 = mbase + ra0, ga1 = mbase + ra1;
    if (permA){ ga0 = (ga0 & 63)*64 + (ga0 >> 6); ga1 = (ga1 & 63)*64 + (ga1 >> 6); }
    const float* ApR0 = A + (size_t)ga0*K + ca0;
    const float* ApR1 = A + (size_t)ga1*K + ca1;
    const float* BpR  = Bw + (size_t)(nbase + rb)*K + cb;

    int m0 = (wid & 3) * 32;
    int n0 = (wid >> 2) * 32;
    int g = lane >> 2, tg = lane & 3;

    float acc[2][4][4];
    #pragma unroll
    for (int i = 0; i < 2; i++)
        #pragma unroll
        for (int jn = 0; jn < 4; jn++)
            #pragma unroll
            for (int e = 0; e < 4; e++) acc[i][jn][e] = 0.f;

    int nk = K >> 4;
    // prologue: chunk 0
    float4 av0 = *(const float4*)ApR0;
    float4 av1 = *(const float4*)ApR1;
    float4 bv  = *(const float4*)BpR;
    {
        ull hi, lo;
        bsplit4(av0, hi, lo);
        *(ull*)&sAh[0][ra0*16 + ca0] = hi;  *(ull*)&sAl[0][ra0*16 + ca0] = lo;
        bsplit4(av1, hi, lo);
        *(ull*)&sAh[0][ra1*16 + ca1] = hi;  *(ull*)&sAl[0][ra1*16 + ca1] = lo;
        bsplit4(bv, hi, lo);
        *(ull*)&sBh[0][rb*16 + cb] = hi;    *(ull*)&sBl[0][rb*16 + cb] = lo;
    }
    __syncthreads();

    for (int kt = 0; kt < nk; kt++){
        int cur = kt & 1;
        if (kt + 1 < nk){
            av0 = *(const float4*)(ApR0 + (kt+1)*16);
            av1 = *(const float4*)(ApR1 + (kt+1)*16);
            bv  = *(const float4*)(BpR  + (kt+1)*16);
        }

        // load fragments (PTX m16n8k16 layout), hi & lo
        unsigned ah[2][4], al[2][4], bh[4][2], bl[4][2];
        #pragma unroll
        for (int i = 0; i < 2; i++){
            int r0 = (m0 + i*16 + g)*16;
            int r8 = (m0 + i*16 + g + 8)*16;
            ah[i][0] = *(const unsigned*)&sAh[cur][r0 + tg*2];
            ah[i][1] = *(const unsigned*)&sAh[cur][r8 + tg*2];
            ah[i][2] = *(const unsigned*)&sAh[cur][r0 + tg*2 + 8];
            ah[i][3] = *(const unsigned*)&sAh[cur][r8 + tg*2 + 8];
            al[i][0] = *(const unsigned*)&sAl[cur][r0 + tg*2];
            al[i][1] = *(const unsigned*)&sAl[cur][r8 + tg*2];
            al[i][2] = *(const unsigned*)&sAl[cur][r0 + tg*2 + 8];
            al[i][3] = *(const unsigned*)&sAl[cur][r8 + tg*2 + 8];
        }
        #pragma unroll
        for (int jn = 0; jn < 4; jn++){
            int rn = (n0 + jn*8 + g)*16;
            bh[jn][0] = *(const unsigned*)&sBh[cur][rn + tg*2];
            bh[jn][1] = *(const unsigned*)&sBh[cur][rn + tg*2 + 8];
            bl[jn][0] = *(const unsigned*)&sBl[cur][rn + tg*2];
            bl[jn][1] = *(const unsigned*)&sBl[cur][rn + tg*2 + 8];
        }

        // 3-term split-bf16 accumulation
        #pragma unroll
        for (int i = 0; i < 2; i++){
            #pragma unroll
            for (int jn = 0; jn < 4; jn++){
                mma16816(acc[i][jn], ah[i], bh[jn]);
                mma16816(acc[i][jn], ah[i], bl[jn]);
                mma16816(acc[i][jn], al[i], bh[jn]);
            }
        }

        if (kt + 1 < nk){
            int nxt = cur ^ 1;
            ull hi, lo;
            bsplit4(av0, hi, lo);
            *(ull*)&sAh[nxt][ra0*16 + ca0] = hi;  *(ull*)&sAl[nxt][ra0*16 + ca0] = lo;
            bsplit4(av1, hi, lo);
            *(ull*)&sAh[nxt][ra1*16 + ca1] = hi;  *(ull*)&sAl[nxt][ra1*16 + ca1] = lo;
            bsplit4(bv, hi, lo);
            *(ull*)&sBh[nxt][rb*16 + cb] = hi;    *(ull*)&sBl[nxt][rb*16 + cb] = lo;
        }
        __syncthreads();
    }

    // epilogue
    #pragma unroll
    for (int i = 0; i < 2; i++){
        int row0 = mbase + m0 + i*16 + g;
        int row1 = row0 + 8;
        #pragma unroll
        for (int jn = 0; jn < 4; jn++){
            int col = nbase + n0 + jn*8 + tg*2;
            float2 v0 = make_float2(acc[i][jn][0], acc[i][jn][1]);
            float2 v1 = make_float2(acc[i][jn][2], acc[i][jn][3]);
            if (bias){
                float2 bb = *(const float2*)&bias[col];
                v0.x += bb.x; v0.y += bb.y;
                v1.x += bb.x; v1.y += bb.y;
            }
            if (doClip){
                v0.x = fminf(fmaxf(v0.x,-1.f),1.f); v0.y = fminf(fmaxf(v0.y,-1.f),1.f);
                v1.x = fminf(fmaxf(v1.x,-1.f),1.f); v1.y = fminf(fmaxf(v1.y,-1.f),1.f);
            }
            *(float2*)&C[(size_t)row0*N + col] = v0;
            *(float2*)&C[(size_t)row1*N + col] = v1;
        }
    }
}

// ---------------- persistent bidirectional GRU (R6-proven, verbatim) ----------
__global__ __launch_bounds__(256) void k_gru(const float* __restrict__ w_hh_f,
                                             const float* __restrict__ w_hh_b,
                                             const float* __restrict__ b_hh_f,
                                             const float* __restrict__ b_hh_b,
                                             float* __restrict__ states){
    extern __shared__ float sm[];
    float4* hs4 = (float4*)(sm + 49152);   // h image: 16 rows x 128 float4 (32KB)

    int blk = blockIdx.x;        // 128
    int dir = blk >> 6;
    int rr = blk & 63;
    int jc = rr >> 2, bq = rr & 3;
    int jbase = jc * 32;
    int bbase = bq * 16;
    int grp = dir*4 + bq;        // 0..7
    const float* whh = dir ? w_hh_b : w_hh_f;
    const float* bhh = dir ? b_hh_b : b_hh_f;
    const float* xg = g_xg[dir];
    int tid = threadIdx.x;
    int jp = tid >> 3;           // 0..31
    int bp = tid & 7;            // 0..7
    int j  = jbase + jp;
    int b0 = bbase + bp*2;
    int bL0 = bp*2, bL1 = bp*2 + 1;
    unsigned key = (unsigned)bp;  // 0..7

    // weights: 96 rows (g*32 + jl). float4 dst = ((g*8 + (jl>>2))*128 + kq)*4 + (jl&3)
    {
        const float4* w4 = (const float4*)whh;
        float4* d4 = (float4*)sm;
        for (int idx = tid; idx < 96*128; idx += 256){
            int row = idx >> 7;          // g*32 + jl
            int kq = idx & 127;
            int g = row >> 5, jl = row & 31;
            int dst = ((g*8 + (jl>>2))*128 + kq)*4 + (jl & 3);
            d4[dst] = w4[(size_t)(g*H_ + jbase + jl)*128 + kq];
        }
    }

    float bhr = bhh[j], bhz = bhh[H_+j], bhn = bhh[2*H_+j];

    g_h2[dir][0][(size_t)b0*H_ + j]     = 0.f;
    g_h2[dir][0][(size_t)(b0+1)*H_ + j] = 0.f;
    gbar_grp(grp);

    const ulonglong2* wu = (const ulonglong2*)sm;
    int wbr = ((0*8 + (jp>>2))*128)*4 + (jp & 3);
    int wbz = ((1*8 + (jp>>2))*128)*4 + (jp & 3);
    int wbn = ((2*8 + (jp>>2))*128)*4 + (jp & 3);
    const ulonglong2* h0row = (const ulonglong2*)(hs4 + bL0*128);
    const ulonglong2* h1row = (const ulonglong2*)(hs4 + bL1*128);

    // preload xg for t=0
    int tidx0 = dir ? (S_-1) : 0;
    const float* xA0 = xg + ((size_t)(tidx0*B_ + b0))*H3_;
    const float* xB0 = xA0 + H3_;
    float xr0 = xA0[j], xz0 = xA0[H_+j], xn0 = xA0[2*H_+j];
    float xr1 = xB0[j], xz1 = xB0[H_+j], xn1 = xB0[2*H_+j];

    for (int t = 0; t < S_; t++){
        int tidx = dir ? (S_-1-t) : t;

        // stage this group's 16 h rows (32KB), coalesced LDG -> swizzled STS
        const float4* hr4 = (const float4*)(g_h2[dir][t & 1] + (size_t)bbase*H_);
        #pragma unroll
        for (int i = 0; i < 8; i++){
            int gi = tid + (i << 8);
            int bb = gi >> 7, kq = gi & 127;
            hs4[bb*128 + (kq ^ ((unsigned)(bb >> 1) & 7u))] = hr4[gi];
        }
        __syncthreads();

        // issue next step's xg loads (hidden under the FMA loop)
        float nxr0=0,nxz0=0,nxn0=0,nxr1=0,nxz1=0,nxn1=0;
        if (t + 1 < S_){
            int ntidx = dir ? (S_-2-t) : (t+1);
            const float* nA = xg + ((size_t)(ntidx*B_ + b0))*H3_;
            const float* nB = nA + H3_;
            nxr0 = nA[j]; nxz0 = nA[H_+j]; nxn0 = nA[2*H_+j];
            nxr1 = nB[j]; nxz1 = nB[H_+j]; nxn1 = nB[2*H_+j];
        }

        ull ar0=0,ar1=0,az0=0,az1=0,an0=0,an1=0;
        #pragma unroll 4
        for (int kq = 0; kq < 128; kq++){
            ulonglong2 hA = h0row[kq ^ key];
            ulonglong2 hB = h1row[kq ^ key];
            int k4 = kq << 2;
            ulonglong2 w;
            w = wu[wbr + k4];
            fma2(ar0, hA.x, w.x); fma2(ar0, hA.y, w.y);
            fma2(ar1, hB.x, w.x); fma2(ar1, hB.y, w.y);
            w = wu[wbz + k4];
            fma2(az0, hA.x, w.x); fma2(az0, hA.y, w.y);
            fma2(az1, hB.x, w.x); fma2(az1, hB.y, w.y);
            w = wu[wbn + k4];
            fma2(an0, hA.x, w.x); fma2(an0, hA.y, w.y);
            fma2(an1, hB.x, w.x); fma2(an1, hB.y, w.y);
        }

        int kqj = j >> 2, jo = j & 3;
        float hp0 = ((const float*)(hs4 + bL0*128 + ((unsigned)kqj ^ key)))[jo];
        float hp1 = ((const float*)(hs4 + bL1*128 + ((unsigned)kqj ^ key)))[jo];

        U64F2 u;
        u.u=ar0; float sr0=u.f.x+u.f.y;  u.u=ar1; float sr1=u.f.x+u.f.y;
        u.u=az0; float sz0=u.f.x+u.f.y;  u.u=az1; float sz1=u.f.x+u.f.y;
        u.u=an0; float sn0=u.f.x+u.f.y;  u.u=an1; float sn1=u.f.x+u.f.y;

        float r0 = 1.f/(1.f+expf(-(xr0 + sr0 + bhr)));
        float r1 = 1.f/(1.f+expf(-(xr1 + sr1 + bhr)));
        float z0 = 1.f/(1.f+expf(-(xz0 + sz0 + bhz)));
        float z1 = 1.f/(1.f+expf(-(xz1 + sz1 + bhz)));
        float n0 = tanhf(xn0 + r0*(sn0 + bhn));
        float n1 = tanhf(xn1 + r1*(sn1 + bhn));
        float h0 = (1.f-z0)*n0 + z0*hp0;
        float h1 = (1.f-z1)*n1 + z1*hp1;

        float* hw = g_h2[dir][(t & 1) ^ 1];
        hw[(size_t)b0*H_ + j]     = h0;
        hw[(size_t)(b0+1)*H_ + j] = h1;
        states[((size_t)b0*S_ + tidx)*(2*H_) + dir*H_ + j]     = h0;
        states[((size_t)(b0+1)*S_ + tidx)*(2*H_) + dir*H_ + j] = h1;

        gbar_grp(grp);

        xr0=nxr0; xz0=nxz0; xn0=nxn0; xr1=nxr1; xz1=nxz1; xn1=nxn1;
    }
}

// ---------------- alpha = m1 @ att_w2^T, softmax over S -----------------------
__global__ __launch_bounds__(256) void k_alpha(const float* __restrict__ att_w2,
                                               float* __restrict__ alpha_out){
    __shared__ float w2s[NH_*A_];
    __shared__ float al[NH_*S_];
    int b = blockIdx.x, tid = threadIdx.x;
    for (int i = tid; i < NH_*A_; i += 256) w2s[i] = att_w2[i];
    __syncthreads();
    int s = tid >> 2, h = tid & 3;
    const float* m1r = g_m1 + ((size_t)(b*S_ + s))*A_;
    float acc = 0.f;
    #pragma unroll 4
    for (int k = 0; k < A_; k++) acc += m1r[k]*w2s[h*A_+k];
    al[h*S_+s] = acc;
    __syncthreads();
    int wid = tid >> 5, lane = tid & 31;
    if (wid < NH_){
        float v0 = al[wid*S_+lane], v1 = al[wid*S_+lane+32];
        float mx = fmaxf(v0, v1);
        #pragma unroll
        for (int o = 16; o > 0; o >>= 1) mx = fmaxf(mx, __shfl_xor_sync(0xffffffffu, mx, o));
        float e0 = expf(v0-mx), e1 = expf(v1-mx);
        float sm = e0 + e1;
        #pragma unroll
        for (int o = 16; o > 0; o >>= 1) sm += __shfl_xor_sync(0xffffffffu, sm, o);
        float inv = 1.f/sm;
        alpha_out[(b*NH_+wid)*S_ + lane]      = e0*inv;
        alpha_out[(b*NH_+wid)*S_ + lane + 32] = e1*inv;
    }
}

// ---------------- context = alpha @ states ------------------------------------
__global__ __launch_bounds__(512) void k_context(const float* __restrict__ states,
                                                 const float* __restrict__ alpha_in,
                                                 float* __restrict__ context){
    __shared__ float als[NH_*S_];
    int b = blockIdx.x, tid = threadIdx.x;
    if (tid < NH_*S_) als[tid] = alpha_in[b*NH_*S_ + tid];
    __syncthreads();
    float a0[NH_], a1[NH_];
    #pragma unroll
    for (int h = 0; h < NH_; h++){ a0[h] = 0.f; a1[h] = 0.f; }
    const float* st = states + (size_t)b*S_*2*H_;
    for (int s = 0; s < S_; s++){
        float v0 = st[s*2*H_ + tid];
        float v1 = st[s*2*H_ + H_ + tid];
        #pragma unroll
        for (int h = 0; h < NH_; h++){
            float a = als[h*S_+s];
            a0[h] += a*v0; a1[h] += a*v1;
        }
    }
    float* cb = context + (size_t)b*NH_*2*H_;
    #pragma unroll
    for (int h = 0; h < NH_; h++){
        cb[h*2*H_ + tid]      = a0[h];
        cb[h*2*H_ + H_ + tid] = a1[h];
    }
}

// ---------------- final linear + softmax --------------------------------------
__global__ __launch_bounds__(512) void k_final(const float* __restrict__ context,
                                               const float* __restrict__ lin_w,
                                               const float* __restrict__ lin_b,
                                               float* __restrict__ out){
    __shared__ float red[OUT_];
    int b = blockIdx.x, tid = threadIdx.x, w = tid >> 5, lane = tid & 31;
    const float* cx = context + (size_t)b*4096;
    const float* lw = lin_w + (size_t)w*4096;
    float acc = 0.f;
    for (int k = lane; k < 4096; k += 32) acc += cx[k]*lw[k];
    #pragma unroll
    for (int o = 16; o > 0; o >>= 1) acc += __shfl_xor_sync(0xffffffffu, acc, o);
    if (lane == 0) red[w] = acc + lin_b[w];
    __syncthreads();
    if (tid < 32){
        float v = (lane < OUT_) ? red[lane] : -1e30f;
        float mx = v;
        #pragma unroll
        for (int o = 16; o > 0; o >>= 1) mx = fmaxf(mx, __shfl_xor_sync(0xffffffffu, mx, o));
        float e = (lane < OUT_) ? expf(v - mx) : 0.f;
        float sm = e;
        #pragma unroll
        for (int o = 16; o > 0; o >>= 1) sm += __shfl_xor_sync(0xffffffffu, sm, o);
        if (lane < OUT_) out[b*OUT_ + lane] = e/sm;
    }
}

// ---------------- launch ------------------------------------------------------
extern "C" void kernel_launch(void* const* d_in, const int* in_sizes, int n_in,
                              void* d_out, int out_size){
    const float* inputs  = (const float*)d_in[0];
    const float* conv_w  = (const float*)d_in[2];
    const float* conv_b  = (const float*)d_in[3];
    const float* w_embed = (const float*)d_in[4];
    const float* w_ih_f  = (const float*)d_in[5];
    const float* w_hh_f  = (const float*)d_in[6];
    const float* b_ih_f  = (const float*)d_in[7];
    const float* b_hh_f  = (const float*)d_in[8];
    const float* w_ih_b  = (const float*)d_in[9];
    const float* w_hh_b  = (const float*)d_in[10];
    const float* b_ih_b  = (const float*)d_in[11];
    const float* b_hh_b  = (const float*)d_in[12];
    const float* att_w1  = (const float*)d_in[13];
    const float* att_w2  = (const float*)d_in[14];
    const float* lin_w   = (const float*)d_in[15];
    const float* lin_b   = (const float*)d_in[16];

    float* out     = (float*)d_out;
    float* states  = out + STATES_OFF;
    float* context = out + CONTEXT_OFF;
    float* alpha   = out + ALPHA_OFF;

    void *p_vec, *p_emb, *p_xg, *p_m1;
    cudaGetSymbolAddress(&p_vec, g_vec);
    cudaGetSymbolAddress(&p_emb, g_emb);
    cudaGetSymbolAddress(&p_xg,  g_xg);
    cudaGetSymbolAddress(&p_m1,  g_m1);
    float* vec = (float*)p_vec;
    float* emb = (float*)p_emb;
    float* xg0 = (float*)p_xg;
    float* m1  = (float*)p_m1;

    const int conv_smem = P_*D_*4;                     // 65536
    const int gru_smem  = 49152*4 + 16*128*16;         // 192KB + 32KB = 229376
    cudaFuncSetAttribute(k_conv_vec, cudaFuncAttributeMaxDynamicSharedMemorySize, conv_smem);
    cudaFuncSetAttribute(k_gru,      cudaFuncAttributeMaxDynamicSharedMemorySize, gru_smem);

    // 1) conv + weighted-sum (inputs read once)
    k_conv_vec<<<BS_, 256, conv_smem>>>(inputs, conv_w, conv_b);
    // 2) emb = clip(vec @ w_embed^T)  [split-bf16 HMMA]
    k_bgemm<<<dim3(E_/64, BS_/128, 1), 256>>>(vec, w_embed, w_embed, emb,
                                              BS_, E_, D_, nullptr, nullptr, 1, 0);
    // 3) xg = emb([S,B] permuted) @ w_ih^T + b_ih, BOTH dirs via grid.z
    k_bgemm<<<dim3(H3_/64, BS_/128, 2), 256>>>(emb, w_ih_f, w_ih_b, xg0,
                                               BS_, H3_, E_, b_ih_f, b_ih_b, 0, 1);
    // 4) persistent bidirectional GRU -> states (written straight into d_out)
    k_gru<<<128, 256, gru_smem>>>(w_hh_f, w_hh_b, b_hh_f, b_hh_b, states);
    // 5) m1 = clip(states @ att_w1^T)  [split-bf16 HMMA]
    k_bgemm<<<dim3(A_/64, BS_/128, 1), 256>>>(states, att_w1, att_w1, m1,
                                              BS_, A_, 2*H_, nullptr, nullptr, 1, 0);
    // 6) alpha = softmax_S(m1 @ att_w2^T), transposed to [B,NH,S]
    k_alpha<<<B_, 256>>>(att_w2, alpha);
    // 7) context
    k_context<<<B_, 512>>>(states, alpha, context);
    // 8) out = softmax(context @ lin_w^T + lin_b)
    k_final<<<B_, 512>>>(context, lin_w, lin_b, out);
}

// round 12
// speedup vs baseline: 1.3923x; 1.2142x over previous
#include <cuda_runtime.h>
#include <cuda_bf16.h>
#include <cstdint>
#include <cstdio>

#define B_ 64
#define S_ 64
#define P_ 32
#define D_ 512
#define E_ 512
#define H_ 512
#define H3_ 1536
#define A_ 256
#define NH_ 4
#define OUT_ 16
#define BS_ (B_*S_)

// d_out layout: out[64,16] | states[B,S,2H] | context[B,4096] | alpha_actv[B,NH,S]
#define STATES_OFF 1024
#define CONTEXT_OFF (1024 + BS_*2*H_)
#define ALPHA_OFF (CONTEXT_OFF + B_*NH_*2*H_)

#define WPAD 516   // padded row stride (bf16 elems): 1032B, 8B-aligned, ~2-way LDS conflicts

// ---------------- scratch (device globals; no allocation allowed) -------------
__device__ float g_vec[BS_*D_];
__device__ float g_emb[BS_*E_];
__device__ float g_xg[2][BS_*H3_];
__device__ float g_h2[2][2][B_*H_];     // [dir][buf][b*H+j]
__device__ float g_m1[BS_*A_];
__device__ unsigned g_cnt8[8][32];      // 8 barrier groups, padded
__device__ unsigned g_gen8[8][32];

typedef unsigned long long ull;

union U64F2 { ull u; float2 f; };

// ---------------- simple group grid barrier (16 blocks per group, R6-proven) --
__device__ __forceinline__ void gbar_grp(int grp){
    __syncthreads();
    if (threadIdx.x == 0){
        __threadfence();
        unsigned g = *((volatile unsigned*)&g_gen8[grp][0]);
        if (atomicAdd(&g_cnt8[grp][0], 1u) == 15u){
            g_cnt8[grp][0] = 0u;
            __threadfence();
            atomicExch(&g_gen8[grp][0], g + 1u);
        } else {
            while (*((volatile unsigned*)&g_gen8[grp][0]) == g) { }
        }
        __threadfence();
    }
    __syncthreads();
}

// ---------------- split-bf16 helpers (validated in R11) ------------------------
__device__ __forceinline__ void bsplit4(float4 v, ull& hi, ull& lo){
    __nv_bfloat16 h0 = __float2bfloat16_rn(v.x);
    __nv_bfloat16 h1 = __float2bfloat16_rn(v.y);
    __nv_bfloat16 h2 = __float2bfloat16_rn(v.z);
    __nv_bfloat16 h3 = __float2bfloat16_rn(v.w);
    __nv_bfloat16 l0 = __float2bfloat16_rn(v.x - __bfloat162float(h0));
    __nv_bfloat16 l1 = __float2bfloat16_rn(v.y - __bfloat162float(h1));
    __nv_bfloat16 l2 = __float2bfloat16_rn(v.z - __bfloat162float(h2));
    __nv_bfloat16 l3 = __float2bfloat16_rn(v.w - __bfloat162float(h3));
    hi = (ull)__bfloat16_as_ushort(h0) | ((ull)__bfloat16_as_ushort(h1) << 16)
       | ((ull)__bfloat16_as_ushort(h2) << 32) | ((ull)__bfloat16_as_ushort(h3) << 48);
    lo = (ull)__bfloat16_as_ushort(l0) | ((ull)__bfloat16_as_ushort(l1) << 16)
       | ((ull)__bfloat16_as_ushort(l2) << 32) | ((ull)__bfloat16_as_ushort(l3) << 48);
}
__device__ __forceinline__ void mma16816(float* c, const unsigned* a, const unsigned* b){
    asm volatile(
        "mma.sync.aligned.m16n8k16.row.col.f32.bf16.bf16.f32 "
        "{%0,%1,%2,%3}, {%4,%5,%6,%7}, {%8,%9}, {%0,%1,%2,%3};"
        : "+f"(c[0]), "+f"(c[1]), "+f"(c[2]), "+f"(c[3])
        : "r"(a[0]), "r"(a[1]), "r"(a[2]), "r"(a[3]), "r"(b[0]), "r"(b[1]));
}

// ---------------- fused conv + weighted-sum (reads inputs ONCE) ---------------
__global__ __launch_bounds__(256) void k_conv_vec(const float* __restrict__ inp,
                                                  const float* __restrict__ conv_w,
                                                  const float* __restrict__ conv_b){
    extern __shared__ float tile[];          // P_*D_ = 16384 floats = 64KB
    __shared__ float cw[D_];
    __shared__ float convp[P_];
    int bs = blockIdx.x;
    int tid = threadIdx.x;
    const float4* src4 = (const float4*)(inp + (size_t)bs*P_*D_);
    float4* t4 = (float4*)tile;
    for (int i = tid; i < D_; i += 256) cw[i] = conv_w[i];
    for (int i = tid; i < P_*D_/4; i += 256) t4[i] = src4[i];
    __syncthreads();
    int wid = tid >> 5, lane = tid & 31;
    float cb = conv_b[0];
    for (int p = wid; p < P_; p += 8){
        float s = 0.f;
        for (int d = lane; d < D_; d += 32) s += tile[p*D_+d]*cw[d];
        #pragma unroll
        for (int o = 16; o > 0; o >>= 1) s += __shfl_xor_sync(0xffffffffu, s, o);
        if (lane == 0) convp[p] = s + cb;
    }
    __syncthreads();
    for (int d = tid; d < D_; d += 256){
        float acc = 0.f;
        #pragma unroll
        for (int p = 0; p < P_; p++) acc += convp[p]*tile[p*D_+d];
        g_vec[(size_t)bs*D_ + d] = acc;
    }
}

// ---------------- split-bf16 HMMA GEMM (R11-proven): C = A @ Bw^T --------------
__global__ __launch_bounds__(256) void k_bgemm(const float* __restrict__ A,
                                               const float* __restrict__ Bw,
                                               const float* __restrict__ Bw2,
                                               float* __restrict__ C,
                                               int M, int N, int K,
                                               const float* __restrict__ bias,
                                               const float* __restrict__ bias2,
                                               int doClip, int permA){
    __shared__ __align__(16) unsigned short sAh[2][128*16];
    __shared__ __align__(16) unsigned short sAl[2][128*16];
    __shared__ __align__(16) unsigned short sBh[2][64*16];
    __shared__ __align__(16) unsigned short sBl[2][64*16];

    int tid = threadIdx.x;
    int wid = tid >> 5, lane = tid & 31;
    if (blockIdx.z){ Bw = Bw2; bias = bias2; C += (size_t)M*N; }
    int mbase = blockIdx.y * 128;
    int nbase = blockIdx.x * 64;

    int ia0 = tid*2, ia1 = tid*2 + 1;
    int ra0 = ia0 >> 2, ca0 = (ia0 & 3)*4;
    int ra1 = ia1 >> 2, ca1 = (ia1 & 3)*4;
    int rb  = tid >> 2, cb = (tid & 3)*4;
    int ga0 = mbase + ra0, ga1 = mbase + ra1;
    if (permA){ ga0 = (ga0 & 63)*64 + (ga0 >> 6); ga1 = (ga1 & 63)*64 + (ga1 >> 6); }
    const float* ApR0 = A + (size_t)ga0*K + ca0;
    const float* ApR1 = A + (size_t)ga1*K + ca1;
    const float* BpR  = Bw + (size_t)(nbase + rb)*K + cb;

    int m0 = (wid & 3) * 32;
    int n0 = (wid >> 2) * 32;
    int g = lane >> 2, tg = lane & 3;

    float acc[2][4][4];
    #pragma unroll
    for (int i = 0; i < 2; i++)
        #pragma unroll
        for (int jn = 0; jn < 4; jn++)
            #pragma unroll
            for (int e = 0; e < 4; e++) acc[i][jn][e] = 0.f;

    int nk = K >> 4;
    float4 av0 = *(const float4*)ApR0;
    float4 av1 = *(const float4*)ApR1;
    float4 bv  = *(const float4*)BpR;
    {
        ull hi, lo;
        bsplit4(av0, hi, lo);
        *(ull*)&sAh[0][ra0*16 + ca0] = hi;  *(ull*)&sAl[0][ra0*16 + ca0] = lo;
        bsplit4(av1, hi, lo);
        *(ull*)&sAh[0][ra1*16 + ca1] = hi;  *(ull*)&sAl[0][ra1*16 + ca1] = lo;
        bsplit4(bv, hi, lo);
        *(ull*)&sBh[0][rb*16 + cb] = hi;    *(ull*)&sBl[0][rb*16 + cb] = lo;
    }
    __syncthreads();

    for (int kt = 0; kt < nk; kt++){
        int cur = kt & 1;
        if (kt + 1 < nk){
            av0 = *(const float4*)(ApR0 + (kt+1)*16);
            av1 = *(const float4*)(ApR1 + (kt+1)*16);
            bv  = *(const float4*)(BpR  + (kt+1)*16);
        }

        unsigned ah[2][4], al[2][4], bh[4][2], bl[4][2];
        #pragma unroll
        for (int i = 0; i < 2; i++){
            int r0 = (m0 + i*16 + g)*16;
            int r8 = (m0 + i*16 + g + 8)*16;
            ah[i][0] = *(const unsigned*)&sAh[cur][r0 + tg*2];
            ah[i][1] = *(const unsigned*)&sAh[cur][r8 + tg*2];
            ah[i][2] = *(const unsigned*)&sAh[cur][r0 + tg*2 + 8];
            ah[i][3] = *(const unsigned*)&sAh[cur][r8 + tg*2 + 8];
            al[i][0] = *(const unsigned*)&sAl[cur][r0 + tg*2];
            al[i][1] = *(const unsigned*)&sAl[cur][r8 + tg*2];
            al[i][2] = *(const unsigned*)&sAl[cur][r0 + tg*2 + 8];
            al[i][3] = *(const unsigned*)&sAl[cur][r8 + tg*2 + 8];
        }
        #pragma unroll
        for (int jn = 0; jn < 4; jn++){
            int rn = (n0 + jn*8 + g)*16;
            bh[jn][0] = *(const unsigned*)&sBh[cur][rn + tg*2];
            bh[jn][1] = *(const unsigned*)&sBh[cur][rn + tg*2 + 8];
            bl[jn][0] = *(const unsigned*)&sBl[cur][rn + tg*2];
            bl[jn][1] = *(const unsigned*)&sBl[cur][rn + tg*2 + 8];
        }

        #pragma unroll
        for (int i = 0; i < 2; i++){
            #pragma unroll
            for (int jn = 0; jn < 4; jn++){
                mma16816(acc[i][jn], ah[i], bh[jn]);
                mma16816(acc[i][jn], ah[i], bl[jn]);
                mma16816(acc[i][jn], al[i], bh[jn]);
            }
        }

        if (kt + 1 < nk){
            int nxt = cur ^ 1;
            ull hi, lo;
            bsplit4(av0, hi, lo);
            *(ull*)&sAh[nxt][ra0*16 + ca0] = hi;  *(ull*)&sAl[nxt][ra0*16 + ca0] = lo;
            bsplit4(av1, hi, lo);
            *(ull*)&sAh[nxt][ra1*16 + ca1] = hi;  *(ull*)&sAl[nxt][ra1*16 + ca1] = lo;
            bsplit4(bv, hi, lo);
            *(ull*)&sBh[nxt][rb*16 + cb] = hi;    *(ull*)&sBl[nxt][rb*16 + cb] = lo;
        }
        __syncthreads();
    }

    #pragma unroll
    for (int i = 0; i < 2; i++){
        int row0 = mbase + m0 + i*16 + g;
        int row1 = row0 + 8;
        #pragma unroll
        for (int jn = 0; jn < 4; jn++){
            int col = nbase + n0 + jn*8 + tg*2;
            float2 v0 = make_float2(acc[i][jn][0], acc[i][jn][1]);
            float2 v1 = make_float2(acc[i][jn][2], acc[i][jn][3]);
            if (bias){
                float2 bb = *(const float2*)&bias[col];
                v0.x += bb.x; v0.y += bb.y;
                v1.x += bb.x; v1.y += bb.y;
            }
            if (doClip){
                v0.x = fminf(fmaxf(v0.x,-1.f),1.f); v0.y = fminf(fmaxf(v0.y,-1.f),1.f);
                v1.x = fminf(fmaxf(v1.x,-1.f),1.f); v1.y = fminf(fmaxf(v1.y,-1.f),1.f);
            }
            *(float2*)&C[(size_t)row0*N + col] = v0;
            *(float2*)&C[(size_t)row1*N + col] = v1;
        }
    }
}

// ---------------- persistent bidirectional GRU v9: HMMA recurrence ------------
// R6 geometry (128 blocks, 32j x 16b, 8 groups of 16, same barrier), but the
// per-step matvec is a 96x16x512 split-bf16 HMMA GEMM:
//   weights hi/lo resident in smem (96 x WPAD rows), h split hi/lo each step.
// 6 mma warps own one 16-row m-tile each; accum dump -> smem -> gate epilogue.
__global__ __launch_bounds__(256) void k_gru(const float* __restrict__ w_hh_f,
                                             const float* __restrict__ w_hh_b,
                                             const float* __restrict__ b_hh_f,
                                             const float* __restrict__ b_hh_b,
                                             float* __restrict__ states){
    extern __shared__ unsigned short smu[];
    unsigned short* wHi = smu;                       // 96*WPAD
    unsigned short* wLo = smu + 96*WPAD;             // 96*WPAD
    unsigned short* hHi = smu + 192*WPAD;            // 16*WPAD
    unsigned short* hLo = hHi + 16*WPAD;             // 16*WPAD
    float* epi = (float*)hHi;                        // 96*16 floats, reused post-mma

    int blk = blockIdx.x;        // 128
    int dir = blk >> 6;
    int rr = blk & 63;
    int jc = rr >> 2, bq = rr & 3;
    int jbase = jc * 32;
    int bbase = bq * 16;
    int grp = dir*4 + bq;        // 0..7
    const float* whh = dir ? w_hh_b : w_hh_f;
    const float* bhh = dir ? b_hh_b : b_hh_f;
    const float* xg = g_xg[dir];
    int tid = threadIdx.x;
    int wid = tid >> 5, lane = tid & 31;
    int g = lane >> 2, tg = lane & 3;
    int jp = tid >> 3;           // 0..31
    int bp = tid & 7;            // 0..7
    int j  = jbase + jp;
    int b0 = bbase + bp*2;

    // ---- one-time: load + split weights (rows: gate*32 + jl) ----
    {
        const float4* w4 = (const float4*)whh;
        for (int idx = tid; idx < 96*128; idx += 256){
            int row = idx >> 7;          // gate*32 + jl
            int kq = idx & 127;
            int gg = row >> 5, jl = row & 31;
            float4 v = w4[(size_t)(gg*H_ + jbase + jl)*128 + kq];
            ull hi, lo;
            bsplit4(v, hi, lo);
            *(ull*)&wHi[row*WPAD + kq*4] = hi;
            *(ull*)&wLo[row*WPAD + kq*4] = lo;
        }
    }

    float bhr = bhh[j], bhz = bhh[H_+j], bhn = bhh[2*H_+j];

    g_h2[dir][0][(size_t)b0*H_ + j]     = 0.f;
    g_h2[dir][0][(size_t)(b0+1)*H_ + j] = 0.f;
    gbar_grp(grp);

    // preload xg for t=0
    int tidx0 = dir ? (S_-1) : 0;
    const float* xA0 = xg + ((size_t)(tidx0*B_ + b0))*H3_;
    const float* xB0 = xA0 + H3_;
    float xr0 = xA0[j], xz0 = xA0[H_+j], xn0 = xA0[2*H_+j];
    float xr1 = xB0[j], xz1 = xB0[H_+j], xn1 = xB0[2*H_+j];

    int m0r = wid * 16;          // mma warp's row base (wid < 6)

    for (int t = 0; t < S_; t++){
        int tidx = dir ? (S_-1-t) : t;
        const float* hprev = g_h2[dir][t & 1];

        // stage h: split 16 rows x 512 fp32 -> bf16 hi/lo in smem
        const float4* hr4 = (const float4*)(hprev + (size_t)bbase*H_);
        #pragma unroll
        for (int i = 0; i < 8; i++){
            int gi = tid + (i << 8);
            int bb = gi >> 7, kq = gi & 127;
            ull hi, lo;
            bsplit4(hr4[gi], hi, lo);
            *(ull*)&hHi[bb*WPAD + kq*4] = hi;
            *(ull*)&hLo[bb*WPAD + kq*4] = lo;
        }
        // hp + next xg issued early (hidden under mma)
        float hp0 = hprev[(size_t)b0*H_ + j];
        float hp1 = hprev[(size_t)(b0+1)*H_ + j];
        float nxr0=0,nxz0=0,nxn0=0,nxr1=0,nxz1=0,nxn1=0;
        if (t + 1 < S_){
            int ntidx = dir ? (S_-2-t) : (t+1);
            const float* nA = xg + ((size_t)(ntidx*B_ + b0))*H3_;
            const float* nB = nA + H3_;
            nxr0 = nA[j]; nxz0 = nA[H_+j]; nxn0 = nA[2*H_+j];
            nxr1 = nB[j]; nxz1 = nB[H_+j]; nxn1 = nB[2*H_+j];
        }
        __syncthreads();

        float acc0[4] = {0.f,0.f,0.f,0.f};
        float acc1[4] = {0.f,0.f,0.f,0.f};
        if (wid < 6){
            int rA0 = (m0r + g)*WPAD;
            int rA8 = (m0r + g + 8)*WPAD;
            int rB0 = g*WPAD;
            int rB8 = (8 + g)*WPAD;
            #pragma unroll 4
            for (int kc = 0; kc < 32; kc++){
                int kb = kc*16 + tg*2;
                unsigned ah[4], al[4], b0h[2], b0l[2], b1h[2], b1l[2];
                ah[0] = *(const unsigned*)&wHi[rA0 + kb];
                ah[1] = *(const unsigned*)&wHi[rA8 + kb];
                ah[2] = *(const unsigned*)&wHi[rA0 + kb + 8];
                ah[3] = *(const unsigned*)&wHi[rA8 + kb + 8];
                al[0] = *(const unsigned*)&wLo[rA0 + kb];
                al[1] = *(const unsigned*)&wLo[rA8 + kb];
                al[2] = *(const unsigned*)&wLo[rA0 + kb + 8];
                al[3] = *(const unsigned*)&wLo[rA8 + kb + 8];
                b0h[0] = *(const unsigned*)&hHi[rB0 + kb];
                b0h[1] = *(const unsigned*)&hHi[rB0 + kb + 8];
                b0l[0] = *(const unsigned*)&hLo[rB0 + kb];
                b0l[1] = *(const unsigned*)&hLo[rB0 + kb + 8];
                b1h[0] = *(const unsigned*)&hHi[rB8 + kb];
                b1h[1] = *(const unsigned*)&hHi[rB8 + kb + 8];
                b1l[0] = *(const unsigned*)&hLo[rB8 + kb];
                b1l[1] = *(const unsigned*)&hLo[rB8 + kb + 8];
                mma16816(acc0, ah, b0h);
                mma16816(acc0, ah, b0l);
                mma16816(acc0, al, b0h);
                mma16816(acc1, ah, b1h);
                mma16816(acc1, ah, b1l);
                mma16816(acc1, al, b1h);
            }
        }
        __syncthreads();   // all hHi/hLo reads done -> safe to reuse as epi

        if (wid < 6){
            int r0 = (m0r + g)*16;
            int r8 = (m0r + g + 8)*16;
            epi[r0 + tg*2]          = acc0[0];
            epi[r0 + tg*2 + 1]      = acc0[1];
            epi[r8 + tg*2]          = acc0[2];
            epi[r8 + tg*2 + 1]      = acc0[3];
            epi[r0 + 8 + tg*2]      = acc1[0];
            epi[r0 + 8 + tg*2 + 1]  = acc1[1];
            epi[r8 + 8 + tg*2]      = acc1[2];
            epi[r8 + 8 + tg*2 + 1]  = acc1[3];
        }
        __syncthreads();

        float sr0 = epi[jp*16 + bp*2],        sr1 = epi[jp*16 + bp*2 + 1];
        float sz0 = epi[(32+jp)*16 + bp*2],   sz1 = epi[(32+jp)*16 + bp*2 + 1];
        float sn0 = epi[(64+jp)*16 + bp*2],   sn1 = epi[(64+jp)*16 + bp*2 + 1];

        float r0 = 1.f/(1.f+expf(-(xr0 + sr0 + bhr)));
        float r1 = 1.f/(1.f+expf(-(xr1 + sr1 + bhr)));
        float z0 = 1.f/(1.f+expf(-(xz0 + sz0 + bhz)));
        float z1 = 1.f/(1.f+expf(-(xz1 + sz1 + bhz)));
        float n0 = tanhf(xn0 + r0*(sn0 + bhn));
        float n1 = tanhf(xn1 + r1*(sn1 + bhn));
        float h0 = (1.f-z0)*n0 + z0*hp0;
        float h1 = (1.f-z1)*n1 + z1*hp1;

        float* hw = g_h2[dir][(t & 1) ^ 1];
        hw[(size_t)b0*H_ + j]     = h0;
        hw[(size_t)(b0+1)*H_ + j] = h1;
        states[((size_t)b0*S_ + tidx)*(2*H_) + dir*H_ + j]     = h0;
        states[((size_t)(b0+1)*S_ + tidx)*(2*H_) + dir*H_ + j] = h1;

        gbar_grp(grp);

        xr0=nxr0; xz0=nxz0; xn0=nxn0; xr1=nxr1; xz1=nxz1; xn1=nxn1;
    }
}

// ---------------- alpha = m1 @ att_w2^T, softmax over S -----------------------
__global__ __launch_bounds__(256) void k_alpha(const float* __restrict__ att_w2,
                                               float* __restrict__ alpha_out){
    __shared__ float w2s[NH_*A_];
    __shared__ float al[NH_*S_];
    int b = blockIdx.x, tid = threadIdx.x;
    for (int i = tid; i < NH_*A_; i += 256) w2s[i] = att_w2[i];
    __syncthreads();
    int s = tid >> 2, h = tid & 3;
    const float* m1r = g_m1 + ((size_t)(b*S_ + s))*A_;
    float acc = 0.f;
    #pragma unroll 4
    for (int k = 0; k < A_; k++) acc += m1r[k]*w2s[h*A_+k];
    al[h*S_+s] = acc;
    __syncthreads();
    int wid = tid >> 5, lane = tid & 31;
    if (wid < NH_){
        float v0 = al[wid*S_+lane], v1 = al[wid*S_+lane+32];
        float mx = fmaxf(v0, v1);
        #pragma unroll
        for (int o = 16; o > 0; o >>= 1) mx = fmaxf(mx, __shfl_xor_sync(0xffffffffu, mx, o));
        float e0 = expf(v0-mx), e1 = expf(v1-mx);
        float sm = e0 + e1;
        #pragma unroll
        for (int o = 16; o > 0; o >>= 1) sm += __shfl_xor_sync(0xffffffffu, sm, o);
        float inv = 1.f/sm;
        alpha_out[(b*NH_+wid)*S_ + lane]      = e0*inv;
        alpha_out[(b*NH_+wid)*S_ + lane + 32] = e1*inv;
    }
}

// ---------------- context = alpha @ states ------------------------------------
__global__ __launch_bounds__(512) void k_context(const float* __restrict__ states,
                                                 const float* __restrict__ alpha_in,
                                                 float* __restrict__ context){
    __shared__ float als[NH_*S_];
    int b = blockIdx.x, tid = threadIdx.x;
    if (tid < NH_*S_) als[tid] = alpha_in[b*NH_*S_ + tid];
    __syncthreads();
    float a0[NH_], a1[NH_];
    #pragma unroll
    for (int h = 0; h < NH_; h++){ a0[h] = 0.f; a1[h] = 0.f; }
    const float* st = states + (size_t)b*S_*2*H_;
    for (int s = 0; s < S_; s++){
        float v0 = st[s*2*H_ + tid];
        float v1 = st[s*2*H_ + H_ + tid];
        #pragma unroll
        for (int h = 0; h < NH_; h++){
            float a = als[h*S_+s];
            a0[h] += a*v0; a1[h] += a*v1;
        }
    }
    float* cb = context + (size_t)b*NH_*2*H_;
    #pragma unroll
    for (int h = 0; h < NH_; h++){
        cb[h*2*H_ + tid]      = a0[h];
        cb[h*2*H_ + H_ + tid] = a1[h];
    }
}

// ---------------- final linear + softmax --------------------------------------
__global__ __launch_bounds__(512) void k_final(const float* __restrict__ context,
                                               const float* __restrict__ lin_w,
                                               const float* __restrict__ lin_b,
                                               float* __restrict__ out){
    __shared__ float red[OUT_];
    int b = blockIdx.x, tid = threadIdx.x, w = tid >> 5, lane = tid & 31;
    const float* cx = context + (size_t)b*4096;
    const float* lw = lin_w + (size_t)w*4096;
    float acc = 0.f;
    for (int k = lane; k < 4096; k += 32) acc += cx[k]*lw[k];
    #pragma unroll
    for (int o = 16; o > 0; o >>= 1) acc += __shfl_xor_sync(0xffffffffu, acc, o);
    if (lane == 0) red[w] = acc + lin_b[w];
    __syncthreads();
    if (tid < 32){
        float v = (lane < OUT_) ? red[lane] : -1e30f;
        float mx = v;
        #pragma unroll
        for (int o = 16; o > 0; o >>= 1) mx = fmaxf(mx, __shfl_xor_sync(0xffffffffu, mx, o));
        float e = (lane < OUT_) ? expf(v - mx) : 0.f;
        float sm = e;
        #pragma unroll
        for (int o = 16; o > 0; o >>= 1) sm += __shfl_xor_sync(0xffffffffu, sm, o);
        if (lane < OUT_) out[b*OUT_ + lane] = e/sm;
    }
}

// ---------------- launch ------------------------------------------------------
extern "C" void kernel_launch(void* const* d_in, const int* in_sizes, int n_in,
                              void* d_out, int out_size){
    const float* inputs  = (const float*)d_in[0];
    const float* conv_w  = (const float*)d_in[2];
    const float* conv_b  = (const float*)d_in[3];
    const float* w_embed = (const float*)d_in[4];
    const float* w_ih_f  = (const float*)d_in[5];
    const float* w_hh_f  = (const float*)d_in[6];
    const float* b_ih_f  = (const float*)d_in[7];
    const float* b_hh_f  = (const float*)d_in[8];
    const float* w_ih_b  = (const float*)d_in[9];
    const float* w_hh_b  = (const float*)d_in[10];
    const float* b_ih_b  = (const float*)d_in[11];
    const float* b_hh_b  = (const float*)d_in[12];
    const float* att_w1  = (const float*)d_in[13];
    const float* att_w2  = (const float*)d_in[14];
    const float* lin_w   = (const float*)d_in[15];
    const float* lin_b   = (const float*)d_in[16];

    float* out     = (float*)d_out;
    float* states  = out + STATES_OFF;
    float* context = out + CONTEXT_OFF;
    float* alpha   = out + ALPHA_OFF;

    void *p_vec, *p_emb, *p_xg, *p_m1;
    cudaGetSymbolAddress(&p_vec, g_vec);
    cudaGetSymbolAddress(&p_emb, g_emb);
    cudaGetSymbolAddress(&p_xg,  g_xg);
    cudaGetSymbolAddress(&p_m1,  g_m1);
    float* vec = (float*)p_vec;
    float* emb = (float*)p_emb;
    float* xg0 = (float*)p_xg;
    float* m1  = (float*)p_m1;

    const int conv_smem = P_*D_*4;                       // 65536
    const int gru_smem  = (192*WPAD + 32*WPAD) * 2;      // 224*516*2 = 231168
    cudaFuncSetAttribute(k_conv_vec, cudaFuncAttributeMaxDynamicSharedMemorySize, conv_smem);
    cudaFuncSetAttribute(k_gru,      cudaFuncAttributeMaxDynamicSharedMemorySize, gru_smem);

    // 1) conv + weighted-sum (inputs read once)
    k_conv_vec<<<BS_, 256, conv_smem>>>(inputs, conv_w, conv_b);
    // 2) emb = clip(vec @ w_embed^T)  [split-bf16 HMMA]
    k_bgemm<<<dim3(E_/64, BS_/128, 1), 256>>>(vec, w_embed, w_embed, emb,
                                              BS_, E_, D_, nullptr, nullptr, 1, 0);
    // 3) xg = emb([S,B] permuted) @ w_ih^T + b_ih, BOTH dirs via grid.z
    k_bgemm<<<dim3(H3_/64, BS_/128, 2), 256>>>(emb, w_ih_f, w_ih_b, xg0,
                                               BS_, H3_, E_, b_ih_f, b_ih_b, 0, 1);
    // 4) persistent bidirectional GRU (HMMA recurrence) -> states
    k_gru<<<128, 256, gru_smem>>>(w_hh_f, w_hh_b, b_hh_f, b_hh_b, states);
    // 5) m1 = clip(states @ att_w1^T)  [split-bf16 HMMA]
    k_bgemm<<<dim3(A_/64, BS_/128, 1), 256>>>(states, att_w1, att_w1, m1,
                                              BS_, A_, 2*H_, nullptr, nullptr, 1, 0);
    // 6) alpha = softmax_S(m1 @ att_w2^T), transposed to [B,NH,S]
    k_alpha<<<B_, 256>>>(att_w2, alpha);
    // 7) context
    k_context<<<B_, 512>>>(states, alpha, context);
    // 8) out = softmax(context @ lin_w^T + lin_b)
    k_final<<<B_, 512>>>(context, lin_w, lin_b, out);
}

// round 13
// speedup vs baseline: 1.5247x; 1.0951x over previous
#include <cuda_runtime.h>
#include <cuda_bf16.h>
#include <cstdint>
#include <cstdio>

#define B_ 64
#define S_ 64
#define P_ 32
#define D_ 512
#define E_ 512
#define H_ 512
#define H3_ 1536
#define A_ 256
#define NH_ 4
#define OUT_ 16
#define BS_ (B_*S_)

// d_out layout: out[64,16] | states[B,S,2H] | context[B,4096] | alpha_actv[B,NH,S]
#define STATES_OFF 1024
#define CONTEXT_OFF (1024 + BS_*2*H_)
#define ALPHA_OFF (CONTEXT_OFF + B_*NH_*2*H_)

#define WPAD 516   // GRU weight row stride (bf16 elems) — unchanged from R12
#define GST 24     // bgemm smem row stride (bf16 elems): 48B, 16B-aligned, conflict-free ldmatrix

// ---------------- scratch (device globals; no allocation allowed) -------------
__device__ float g_vec[BS_*D_];
__device__ float g_emb[BS_*E_];
__device__ float g_xg[2][BS_*H3_];
__device__ float g_h2[2][2][B_*H_];     // [dir][buf][b*H+j]
__device__ float g_m1[BS_*A_];
__device__ unsigned g_cnt8[8][32];      // 8 barrier groups, padded
__device__ unsigned g_gen8[8][32];

typedef unsigned long long ull;

union U64F2 { ull u; float2 f; };

// ---------------- simple group grid barrier (16 blocks per group, R6-proven) --
__device__ __forceinline__ void gbar_grp(int grp){
    __syncthreads();
    if (threadIdx.x == 0){
        __threadfence();
        unsigned g = *((volatile unsigned*)&g_gen8[grp][0]);
        if (atomicAdd(&g_cnt8[grp][0], 1u) == 15u){
            g_cnt8[grp][0] = 0u;
            __threadfence();
            atomicExch(&g_gen8[grp][0], g + 1u);
        } else {
            while (*((volatile unsigned*)&g_gen8[grp][0]) == g) { }
        }
        __threadfence();
    }
    __syncthreads();
}

// ---------------- split-bf16 helpers (validated in R11/R12) --------------------
__device__ __forceinline__ void bsplit4(float4 v, ull& hi, ull& lo){
    __nv_bfloat16 h0 = __float2bfloat16_rn(v.x);
    __nv_bfloat16 h1 = __float2bfloat16_rn(v.y);
    __nv_bfloat16 h2 = __float2bfloat16_rn(v.z);
    __nv_bfloat16 h3 = __float2bfloat16_rn(v.w);
    __nv_bfloat16 l0 = __float2bfloat16_rn(v.x - __bfloat162float(h0));
    __nv_bfloat16 l1 = __float2bfloat16_rn(v.y - __bfloat162float(h1));
    __nv_bfloat16 l2 = __float2bfloat16_rn(v.z - __bfloat162float(h2));
    __nv_bfloat16 l3 = __float2bfloat16_rn(v.w - __bfloat162float(h3));
    hi = (ull)__bfloat16_as_ushort(h0) | ((ull)__bfloat16_as_ushort(h1) << 16)
       | ((ull)__bfloat16_as_ushort(h2) << 32) | ((ull)__bfloat16_as_ushort(h3) << 48);
    lo = (ull)__bfloat16_as_ushort(l0) | ((ull)__bfloat16_as_ushort(l1) << 16)
       | ((ull)__bfloat16_as_ushort(l2) << 32) | ((ull)__bfloat16_as_ushort(l3) << 48);
}
__device__ __forceinline__ void mma16816(float* c, const unsigned* a, const unsigned* b){
    asm volatile(
        "mma.sync.aligned.m16n8k16.row.col.f32.bf16.bf16.f32 "
        "{%0,%1,%2,%3}, {%4,%5,%6,%7}, {%8,%9}, {%0,%1,%2,%3};"
        : "+f"(c[0]), "+f"(c[1]), "+f"(c[2]), "+f"(c[3])
        : "r"(a[0]), "r"(a[1]), "r"(a[2]), "r"(a[3]), "r"(b[0]), "r"(b[1]));
}
__device__ __forceinline__ void ldsm4(unsigned* r, const void* p){
    unsigned a = (unsigned)__cvta_generic_to_shared(p);
    asm volatile("ldmatrix.sync.aligned.m8n8.x4.shared.b16 {%0,%1,%2,%3}, [%4];"
                 : "=r"(r[0]), "=r"(r[1]), "=r"(r[2]), "=r"(r[3]) : "r"(a));
}

// ---------------- fused conv + weighted-sum (reads inputs ONCE) ---------------
__global__ __launch_bounds__(256) void k_conv_vec(const float* __restrict__ inp,
                                                  const float* __restrict__ conv_w,
                                                  const float* __restrict__ conv_b){
    extern __shared__ float tile[];          // P_*D_ = 16384 floats = 64KB
    __shared__ float cw[D_];
    __shared__ float convp[P_];
    int bs = blockIdx.x;
    int tid = threadIdx.x;
    const float4* src4 = (const float4*)(inp + (size_t)bs*P_*D_);
    float4* t4 = (float4*)tile;
    for (int i = tid; i < D_; i += 256) cw[i] = conv_w[i];
    for (int i = tid; i < P_*D_/4; i += 256) t4[i] = src4[i];
    __syncthreads();
    int wid = tid >> 5, lane = tid & 31;
    float cb = conv_b[0];
    for (int p = wid; p < P_; p += 8){
        float s = 0.f;
        for (int d = lane; d < D_; d += 32) s += tile[p*D_+d]*cw[d];
        #pragma unroll
        for (int o = 16; o > 0; o >>= 1) s += __shfl_xor_sync(0xffffffffu, s, o);
        if (lane == 0) convp[p] = s + cb;
    }
    __syncthreads();
    for (int d = tid; d < D_; d += 256){
        float acc = 0.f;
        #pragma unroll
        for (int p = 0; p < P_; p++) acc += convp[p]*tile[p*D_+d];
        g_vec[(size_t)bs*D_ + d] = acc;
    }
}

// ---------------- split-bf16 HMMA GEMM v2 (ldmatrix fragments) -----------------
__global__ __launch_bounds__(256) void k_bgemm(const float* __restrict__ A,
                                               const float* __restrict__ Bw,
                                               const float* __restrict__ Bw2,
                                               float* __restrict__ C,
                                               int M, int N, int K,
                                               const float* __restrict__ bias,
                                               const float* __restrict__ bias2,
                                               int doClip, int permA){
    __shared__ __align__(16) unsigned short sAh[2][128*GST];
    __shared__ __align__(16) unsigned short sAl[2][128*GST];
    __shared__ __align__(16) unsigned short sBh[2][64*GST];
    __shared__ __align__(16) unsigned short sBl[2][64*GST];

    int tid = threadIdx.x;
    int wid = tid >> 5, lane = tid & 31;
    if (blockIdx.z){ Bw = Bw2; bias = bias2; C += (size_t)M*N; }
    int mbase = blockIdx.y * 128;
    int nbase = blockIdx.x * 64;

    int ia0 = tid*2, ia1 = tid*2 + 1;
    int ra0 = ia0 >> 2, ca0 = (ia0 & 3)*4;
    int ra1 = ia1 >> 2, ca1 = (ia1 & 3)*4;
    int rb  = tid >> 2, cb = (tid & 3)*4;
    int ga0 = mbase + ra0, ga1 = mbase + ra1;
    if (permA){ ga0 = (ga0 & 63)*64 + (ga0 >> 6); ga1 = (ga1 & 63)*64 + (ga1 >> 6); }
    const float* ApR0 = A + (size_t)ga0*K + ca0;
    const float* ApR1 = A + (size_t)ga1*K + ca1;
    const float* BpR  = Bw + (size_t)(nbase + rb)*K + cb;

    int m0 = (wid & 3) * 32;
    int n0 = (wid >> 2) * 32;
    int g = lane >> 2, tg = lane & 3;

    // ldmatrix lane addressing
    int rin = lane & 7, sel = lane >> 3;
    int offA0 = (m0 + (sel & 1)*8 + rin)*GST + (sel >> 1)*8;   // tile i=0
    int offA1 = offA0 + 16*GST;                                 // tile i=1
    int offB0 = (n0 + (sel >> 1)*8 + rin)*GST + (sel & 1)*8;   // jn pair 0 (jn 0,1)
    int offB1 = offB0 + 16*GST;                                 // jn pair 1 (jn 2,3)

    float acc[2][4][4];
    #pragma unroll
    for (int i = 0; i < 2; i++)
        #pragma unroll
        for (int jn = 0; jn < 4; jn++)
            #pragma unroll
            for (int e = 0; e < 4; e++) acc[i][jn][e] = 0.f;

    int nk = K >> 4;
    float4 av0 = *(const float4*)ApR0;
    float4 av1 = *(const float4*)ApR1;
    float4 bv  = *(const float4*)BpR;
    {
        ull hi, lo;
        bsplit4(av0, hi, lo);
        *(ull*)&sAh[0][ra0*GST + ca0] = hi;  *(ull*)&sAl[0][ra0*GST + ca0] = lo;
        bsplit4(av1, hi, lo);
        *(ull*)&sAh[0][ra1*GST + ca1] = hi;  *(ull*)&sAl[0][ra1*GST + ca1] = lo;
        bsplit4(bv, hi, lo);
        *(ull*)&sBh[0][rb*GST + cb] = hi;    *(ull*)&sBl[0][rb*GST + cb] = lo;
    }
    __syncthreads();

    for (int kt = 0; kt < nk; kt++){
        int cur = kt & 1;
        if (kt + 1 < nk){
            av0 = *(const float4*)(ApR0 + (kt+1)*16);
            av1 = *(const float4*)(ApR1 + (kt+1)*16);
            bv  = *(const float4*)(BpR  + (kt+1)*16);
        }

        // fragments via ldmatrix: A {r0k0,r8k0,r0k8,r8k8}; B pair {n0k0,n0k8,n8k0,n8k8}
        unsigned ah[2][4], al[2][4], bh[2][4], bl[2][4];
        ldsm4(ah[0], &sAh[cur][offA0]);
        ldsm4(ah[1], &sAh[cur][offA1]);
        ldsm4(al[0], &sAl[cur][offA0]);
        ldsm4(al[1], &sAl[cur][offA1]);
        ldsm4(bh[0], &sBh[cur][offB0]);
        ldsm4(bh[1], &sBh[cur][offB1]);
        ldsm4(bl[0], &sBl[cur][offB0]);
        ldsm4(bl[1], &sBl[cur][offB1]);

        #pragma unroll
        for (int i = 0; i < 2; i++){
            #pragma unroll
            for (int jn = 0; jn < 4; jn++){
                const unsigned* pbh = &bh[jn >> 1][(jn & 1)*2];
                const unsigned* pbl = &bl[jn >> 1][(jn & 1)*2];
                mma16816(acc[i][jn], ah[i], pbh);
                mma16816(acc[i][jn], ah[i], pbl);
                mma16816(acc[i][jn], al[i], pbh);
            }
        }

        if (kt + 1 < nk){
            int nxt = cur ^ 1;
            ull hi, lo;
            bsplit4(av0, hi, lo);
            *(ull*)&sAh[nxt][ra0*GST + ca0] = hi;  *(ull*)&sAl[nxt][ra0*GST + ca0] = lo;
            bsplit4(av1, hi, lo);
            *(ull*)&sAh[nxt][ra1*GST + ca1] = hi;  *(ull*)&sAl[nxt][ra1*GST + ca1] = lo;
            bsplit4(bv, hi, lo);
            *(ull*)&sBh[nxt][rb*GST + cb] = hi;    *(ull*)&sBl[nxt][rb*GST + cb] = lo;
        }
        __syncthreads();
    }

    #pragma unroll
    for (int i = 0; i < 2; i++){
        int row0 = mbase + m0 + i*16 + g;
        int row1 = row0 + 8;
        #pragma unroll
        for (int jn = 0; jn < 4; jn++){
            int col = nbase + n0 + jn*8 + tg*2;
            float2 v0 = make_float2(acc[i][jn][0], acc[i][jn][1]);
            float2 v1 = make_float2(acc[i][jn][2], acc[i][jn][3]);
            if (bias){
                float2 bb = *(const float2*)&bias[col];
                v0.x += bb.x; v0.y += bb.y;
                v1.x += bb.x; v1.y += bb.y;
            }
            if (doClip){
                v0.x = fminf(fmaxf(v0.x,-1.f),1.f); v0.y = fminf(fmaxf(v0.y,-1.f),1.f);
                v1.x = fminf(fmaxf(v1.x,-1.f),1.f); v1.y = fminf(fmaxf(v1.y,-1.f),1.f);
            }
            *(float2*)&C[(size_t)row0*N + col] = v0;
            *(float2*)&C[(size_t)row1*N + col] = v1;
        }
    }
}

// ---------------- persistent bidirectional GRU v9 (R12-proven, verbatim) ------
__global__ __launch_bounds__(256) void k_gru(const float* __restrict__ w_hh_f,
                                             const float* __restrict__ w_hh_b,
                                             const float* __restrict__ b_hh_f,
                                             const float* __restrict__ b_hh_b,
                                             float* __restrict__ states){
    extern __shared__ unsigned short smu[];
    unsigned short* wHi = smu;                       // 96*WPAD
    unsigned short* wLo = smu + 96*WPAD;             // 96*WPAD
    unsigned short* hHi = smu + 192*WPAD;            // 16*WPAD
    unsigned short* hLo = hHi + 16*WPAD;             // 16*WPAD
    float* epi = (float*)hHi;                        // 96*16 floats, reused post-mma

    int blk = blockIdx.x;        // 128
    int dir = blk >> 6;
    int rr = blk & 63;
    int jc = rr >> 2, bq = rr & 3;
    int jbase = jc * 32;
    int bbase = bq * 16;
    int grp = dir*4 + bq;        // 0..7
    const float* whh = dir ? w_hh_b : w_hh_f;
    const float* bhh = dir ? b_hh_b : b_hh_f;
    const float* xg = g_xg[dir];
    int tid = threadIdx.x;
    int wid = tid >> 5, lane = tid & 31;
    int g = lane >> 2, tg = lane & 3;
    int jp = tid >> 3;           // 0..31
    int bp = tid & 7;            // 0..7
    int j  = jbase + jp;
    int b0 = bbase + bp*2;

    // ---- one-time: load + split weights (rows: gate*32 + jl) ----
    {
        const float4* w4 = (const float4*)whh;
        for (int idx = tid; idx < 96*128; idx += 256){
            int row = idx >> 7;          // gate*32 + jl
            int kq = idx & 127;
            int gg = row >> 5, jl = row & 31;
            float4 v = w4[(size_t)(gg*H_ + jbase + jl)*128 + kq];
            ull hi, lo;
            bsplit4(v, hi, lo);
            *(ull*)&wHi[row*WPAD + kq*4] = hi;
            *(ull*)&wLo[row*WPAD + kq*4] = lo;
        }
    }

    float bhr = bhh[j], bhz = bhh[H_+j], bhn = bhh[2*H_+j];

    g_h2[dir][0][(size_t)b0*H_ + j]     = 0.f;
    g_h2[dir][0][(size_t)(b0+1)*H_ + j] = 0.f;
    gbar_grp(grp);

    // preload xg for t=0
    int tidx0 = dir ? (S_-1) : 0;
    const float* xA0 = xg + ((size_t)(tidx0*B_ + b0))*H3_;
    const float* xB0 = xA0 + H3_;
    float xr0 = xA0[j], xz0 = xA0[H_+j], xn0 = xA0[2*H_+j];
    float xr1 = xB0[j], xz1 = xB0[H_+j], xn1 = xB0[2*H_+j];

    int m0r = wid * 16;          // mma warp's row base (wid < 6)

    for (int t = 0; t < S_; t++){
        int tidx = dir ? (S_-1-t) : t;
        const float* hprev = g_h2[dir][t & 1];

        // stage h: split 16 rows x 512 fp32 -> bf16 hi/lo in smem
        const float4* hr4 = (const float4*)(hprev + (size_t)bbase*H_);
        #pragma unroll
        for (int i = 0; i < 8; i++){
            int gi = tid + (i << 8);
            int bb = gi >> 7, kq = gi & 127;
            ull hi, lo;
            bsplit4(hr4[gi], hi, lo);
            *(ull*)&hHi[bb*WPAD + kq*4] = hi;
            *(ull*)&hLo[bb*WPAD + kq*4] = lo;
        }
        // hp + next xg issued early (hidden under mma)
        float hp0 = hprev[(size_t)b0*H_ + j];
        float hp1 = hprev[(size_t)(b0+1)*H_ + j];
        float nxr0=0,nxz0=0,nxn0=0,nxr1=0,nxz1=0,nxn1=0;
        if (t + 1 < S_){
            int ntidx = dir ? (S_-2-t) : (t+1);
            const float* nA = xg + ((size_t)(ntidx*B_ + b0))*H3_;
            const float* nB = nA + H3_;
            nxr0 = nA[j]; nxz0 = nA[H_+j]; nxn0 = nA[2*H_+j];
            nxr1 = nB[j]; nxz1 = nB[H_+j]; nxn1 = nB[2*H_+j];
        }
        __syncthreads();

        float acc0[4] = {0.f,0.f,0.f,0.f};
        float acc1[4] = {0.f,0.f,0.f,0.f};
        if (wid < 6){
            int rA0 = (m0r + g)*WPAD;
            int rA8 = (m0r + g + 8)*WPAD;
            int rB0 = g*WPAD;
            int rB8 = (8 + g)*WPAD;
            #pragma unroll 4
            for (int kc = 0; kc < 32; kc++){
                int kb = kc*16 + tg*2;
                unsigned ah[4], al[4], b0h[2], b0l[2], b1h[2], b1l[2];
                ah[0] = *(const unsigned*)&wHi[rA0 + kb];
                ah[1] = *(const unsigned*)&wHi[rA8 + kb];
                ah[2] = *(const unsigned*)&wHi[rA0 + kb + 8];
                ah[3] = *(const unsigned*)&wHi[rA8 + kb + 8];
                al[0] = *(const unsigned*)&wLo[rA0 + kb];
                al[1] = *(const unsigned*)&wLo[rA8 + kb];
                al[2] = *(const unsigned*)&wLo[rA0 + kb + 8];
                al[3] = *(const unsigned*)&wLo[rA8 + kb + 8];
                b0h[0] = *(const unsigned*)&hHi[rB0 + kb];
                b0h[1] = *(const unsigned*)&hHi[rB0 + kb + 8];
                b0l[0] = *(const unsigned*)&hLo[rB0 + kb];
                b0l[1] = *(const unsigned*)&hLo[rB0 + kb + 8];
                b1h[0] = *(const unsigned*)&hHi[rB8 + kb];
                b1h[1] = *(const unsigned*)&hHi[rB8 + kb + 8];
                b1l[0] = *(const unsigned*)&hLo[rB8 + kb];
                b1l[1] = *(const unsigned*)&hLo[rB8 + kb + 8];
                mma16816(acc0, ah, b0h);
                mma16816(acc0, ah, b0l);
                mma16816(acc0, al, b0h);
                mma16816(acc1, ah, b1h);
                mma16816(acc1, ah, b1l);
                mma16816(acc1, al, b1h);
            }
        }
        __syncthreads();   // all hHi/hLo reads done -> safe to reuse as epi

        if (wid < 6){
            int r0 = (m0r + g)*16;
            int r8 = (m0r + g + 8)*16;
            epi[r0 + tg*2]          = acc0[0];
            epi[r0 + tg*2 + 1]      = acc0[1];
            epi[r8 + tg*2]          = acc0[2];
            epi[r8 + tg*2 + 1]      = acc0[3];
            epi[r0 + 8 + tg*2]      = acc1[0];
            epi[r0 + 8 + tg*2 + 1]  = acc1[1];
            epi[r8 + 8 + tg*2]      = acc1[2];
            epi[r8 + 8 + tg*2 + 1]  = acc1[3];
        }
        __syncthreads();

        float sr0 = epi[jp*16 + bp*2],        sr1 = epi[jp*16 + bp*2 + 1];
        float sz0 = epi[(32+jp)*16 + bp*2],   sz1 = epi[(32+jp)*16 + bp*2 + 1];
        float sn0 = epi[(64+jp)*16 + bp*2],   sn1 = epi[(64+jp)*16 + bp*2 + 1];

        float r0 = 1.f/(1.f+expf(-(xr0 + sr0 + bhr)));
        float r1 = 1.f/(1.f+expf(-(xr1 + sr1 + bhr)));
        float z0 = 1.f/(1.f+expf(-(xz0 + sz0 + bhz)));
        float z1 = 1.f/(1.f+expf(-(xz1 + sz1 + bhz)));
        float n0 = tanhf(xn0 + r0*(sn0 + bhn));
        float n1 = tanhf(xn1 + r1*(sn1 + bhn));
        float h0 = (1.f-z0)*n0 + z0*hp0;
        float h1 = (1.f-z1)*n1 + z1*hp1;

        float* hw = g_h2[dir][(t & 1) ^ 1];
        hw[(size_t)b0*H_ + j]     = h0;
        hw[(size_t)(b0+1)*H_ + j] = h1;
        states[((size_t)b0*S_ + tidx)*(2*H_) + dir*H_ + j]     = h0;
        states[((size_t)(b0+1)*S_ + tidx)*(2*H_) + dir*H_ + j] = h1;

        gbar_grp(grp);

        xr0=nxr0; xz0=nxz0; xn0=nxn0; xr1=nxr1; xz1=nxz1; xn1=nxn1;
    }
}

// ---------------- alpha = m1 @ att_w2^T, softmax over S -----------------------
__global__ __launch_bounds__(256) void k_alpha(const float* __restrict__ att_w2,
                                               float* __restrict__ alpha_out){
    __shared__ float w2s[NH_*A_];
    __shared__ float al[NH_*S_];
    int b = blockIdx.x, tid = threadIdx.x;
    for (int i = tid; i < NH_*A_; i += 256) w2s[i] = att_w2[i];
    __syncthreads();
    int s = tid >> 2, h = tid & 3;
    const float* m1r = g_m1 + ((size_t)(b*S_ + s))*A_;
    float acc = 0.f;
    #pragma unroll 4
    for (int k = 0; k < A_; k++) acc += m1r[k]*w2s[h*A_+k];
    al[h*S_+s] = acc;
    __syncthreads();
    int wid = tid >> 5, lane = tid & 31;
    if (wid < NH_){
        float v0 = al[wid*S_+lane], v1 = al[wid*S_+lane+32];
        float mx = fmaxf(v0, v1);
        #pragma unroll
        for (int o = 16; o > 0; o >>= 1) mx = fmaxf(mx, __shfl_xor_sync(0xffffffffu, mx, o));
        float e0 = expf(v0-mx), e1 = expf(v1-mx);
        float sm = e0 + e1;
        #pragma unroll
        for (int o = 16; o > 0; o >>= 1) sm += __shfl_xor_sync(0xffffffffu, sm, o);
        float inv = 1.f/sm;
        alpha_out[(b*NH_+wid)*S_ + lane]      = e0*inv;
        alpha_out[(b*NH_+wid)*S_ + lane + 32] = e1*inv;
    }
}

// ---------------- context = alpha @ states ------------------------------------
__global__ __launch_bounds__(512) void k_context(const float* __restrict__ states,
                                                 const float* __restrict__ alpha_in,
                                                 float* __restrict__ context){
    __shared__ float als[NH_*S_];
    int b = blockIdx.x, tid = threadIdx.x;
    if (tid < NH_*S_) als[tid] = alpha_in[b*NH_*S_ + tid];
    __syncthreads();
    float a0[NH_], a1[NH_];
    #pragma unroll
    for (int h = 0; h < NH_; h++){ a0[h] = 0.f; a1[h] = 0.f; }
    const float* st = states + (size_t)b*S_*2*H_;
    for (int s = 0; s < S_; s++){
        float v0 = st[s*2*H_ + tid];
        float v1 = st[s*2*H_ + H_ + tid];
        #pragma unroll
        for (int h = 0; h < NH_; h++){
            float a = als[h*S_+s];
            a0[h] += a*v0; a1[h] += a*v1;
        }
    }
    float* cb = context + (size_t)b*NH_*2*H_;
    #pragma unroll
    for (int h = 0; h < NH_; h++){
        cb[h*2*H_ + tid]      = a0[h];
        cb[h*2*H_ + H_ + tid] = a1[h];
    }
}

// ---------------- final linear + softmax --------------------------------------
__global__ __launch_bounds__(512) void k_final(const float* __restrict__ context,
                                               const float* __restrict__ lin_w,
                                               const float* __restrict__ lin_b,
                                               float* __restrict__ out){
    __shared__ float red[OUT_];
    int b = blockIdx.x, tid = threadIdx.x, w = tid >> 5, lane = tid & 31;
    const float* cx = context + (size_t)b*4096;
    const float* lw = lin_w + (size_t)w*4096;
    float acc = 0.f;
    for (int k = lane; k < 4096; k += 32) acc += cx[k]*lw[k];
    #pragma unroll
    for (int o = 16; o > 0; o >>= 1) acc += __shfl_xor_sync(0xffffffffu, acc, o);
    if (lane == 0) red[w] = acc + lin_b[w];
    __syncthreads();
    if (tid < 32){
        float v = (lane < OUT_) ? red[lane] : -1e30f;
        float mx = v;
        #pragma unroll
        for (int o = 16; o > 0; o >>= 1) mx = fmaxf(mx, __shfl_xor_sync(0xffffffffu, mx, o));
        float e = (lane < OUT_) ? expf(v - mx) : 0.f;
        float sm = e;
        #pragma unroll
        for (int o = 16; o > 0; o >>= 1) sm += __shfl_xor_sync(0xffffffffu, sm, o);
        if (lane < OUT_) out[b*OUT_ + lane] = e/sm;
    }
}

// ---------------- launch ------------------------------------------------------
extern "C" void kernel_launch(void* const* d_in, const int* in_sizes, int n_in,
                              void* d_out, int out_size){
    const float* inputs  = (const float*)d_in[0];
    const float* conv_w  = (const float*)d_in[2];
    const float* conv_b  = (const float*)d_in[3];
    const float* w_embed = (const float*)d_in[4];
    const float* w_ih_f  = (const float*)d_in[5];
    const float* w_hh_f  = (const float*)d_in[6];
    const float* b_ih_f  = (const float*)d_in[7];
    const float* b_hh_f  = (const float*)d_in[8];
    const float* w_ih_b  = (const float*)d_in[9];
    const float* w_hh_b  = (const float*)d_in[10];
    const float* b_ih_b  = (const float*)d_in[11];
    const float* b_hh_b  = (const float*)d_in[12];
    const float* att_w1  = (const float*)d_in[13];
    const float* att_w2  = (const float*)d_in[14];
    const float* lin_w   = (const float*)d_in[15];
    const float* lin_b   = (const float*)d_in[16];

    float* out     = (float*)d_out;
    float* states  = out + STATES_OFF;
    float* context = out + CONTEXT_OFF;
    float* alpha   = out + ALPHA_OFF;

    void *p_vec, *p_emb, *p_xg, *p_m1;
    cudaGetSymbolAddress(&p_vec, g_vec);
    cudaGetSymbolAddress(&p_emb, g_emb);
    cudaGetSymbolAddress(&p_xg,  g_xg);
    cudaGetSymbolAddress(&p_m1,  g_m1);
    float* vec = (float*)p_vec;
    float* emb = (float*)p_emb;
    float* xg0 = (float*)p_xg;
    float* m1  = (float*)p_m1;

    const int conv_smem = P_*D_*4;                       // 65536
    const int gru_smem  = (192*WPAD + 32*WPAD) * 2;      // 231168
    cudaFuncSetAttribute(k_conv_vec, cudaFuncAttributeMaxDynamicSharedMemorySize, conv_smem);
    cudaFuncSetAttribute(k_gru,      cudaFuncAttributeMaxDynamicSharedMemorySize, gru_smem);

    // 1) conv + weighted-sum (inputs read once)
    k_conv_vec<<<BS_, 256, conv_smem>>>(inputs, conv_w, conv_b);
    // 2) emb = clip(vec @ w_embed^T)  [split-bf16 HMMA + ldmatrix]
    k_bgemm<<<dim3(E_/64, BS_/128, 1), 256>>>(vec, w_embed, w_embed, emb,
                                              BS_, E_, D_, nullptr, nullptr, 1, 0);
    // 3) xg = emb([S,B] permuted) @ w_ih^T + b_ih, BOTH dirs via grid.z
    k_bgemm<<<dim3(H3_/64, BS_/128, 2), 256>>>(emb, w_ih_f, w_ih_b, xg0,
                                               BS_, H3_, E_, b_ih_f, b_ih_b, 0, 1);
    // 4) persistent bidirectional GRU (HMMA recurrence) -> states
    k_gru<<<128, 256, gru_smem>>>(w_hh_f, w_hh_b, b_hh_f, b_hh_b, states);
    // 5) m1 = clip(states @ att_w1^T)  [split-bf16 HMMA + ldmatrix]
    k_bgemm<<<dim3(A_/64, BS_/128, 1), 256>>>(states, att_w1, att_w1, m1,
                                              BS_, A_, 2*H_, nullptr, nullptr, 1, 0);
    // 6) alpha = softmax_S(m1 @ att_w2^T), transposed to [B,NH,S]
    k_alpha<<<B_, 256>>>(att_w2, alpha);
    // 7) context
    k_context<<<B_, 512>>>(states, alpha, context);
    // 8) out = softmax(context @ lin_w^T + lin_b)
    k_final<<<B_, 512>>>(context, lin_w, lin_b, out);
}

// round 14
// speedup vs baseline: 1.5366x; 1.0078x over previous
#include <cuda_runtime.h>
#include <cuda_bf16.h>
#include <cstdint>
#include <cstdio>

#define B_ 64
#define S_ 64
#define P_ 32
#define D_ 512
#define E_ 512
#define H_ 512
#define H3_ 1536
#define A_ 256
#define NH_ 4
#define OUT_ 16
#define BS_ (B_*S_)

// d_out layout: out[64,16] | states[B,S,2H] | context[B,4096] | alpha_actv[B,NH,S]
#define STATES_OFF 1024
#define CONTEXT_OFF (1024 + BS_*2*H_)
#define ALPHA_OFF (CONTEXT_OFF + B_*NH_*2*H_)

#define WPAD 516   // GRU weight row stride (bf16 elems)
#define GST 24     // bgemm smem row stride (bf16 elems)

// ---------------- scratch (device globals; no allocation allowed) -------------
__device__ float g_vec[BS_*D_];
__device__ float g_emb[BS_*E_];
__device__ float g_xg[2][BS_*H3_];
__device__ float g_m1[BS_*A_];
__device__ unsigned g_cnt8[8][32];      // 8 barrier groups, padded
__device__ unsigned g_gen8[8][32];

typedef unsigned long long ull;

union U64F2 { ull u; float2 f; };

// ---------------- fence-free group grid barrier (16 blocks, acq/rel) ----------
// block writes -> bar.sync -> thread0 release-arrive; waiters ld.acquire poll.
__device__ __forceinline__ void gbar_grp(int grp){
    __syncthreads();
    if (threadIdx.x == 0){
        unsigned* cnt = &g_cnt8[grp][0];
        unsigned* gen = &g_gen8[grp][0];
        unsigned g;
        asm volatile("ld.relaxed.gpu.u32 %0, [%1];" : "=r"(g) : "l"(gen) : "memory");
        unsigned old;
        asm volatile("atom.release.gpu.add.u32 %0, [%1], 1;"
                     : "=r"(old) : "l"(cnt) : "memory");
        if (old == 15u){
            asm volatile("st.relaxed.gpu.u32 [%0], 0;" :: "l"(cnt) : "memory");
            asm volatile("st.release.gpu.u32 [%0], %1;" :: "l"(gen), "r"(g + 1u) : "memory");
        } else {
            unsigned cur;
            do {
                asm volatile("ld.acquire.gpu.u32 %0, [%1];" : "=r"(cur) : "l"(gen) : "memory");
            } while (cur == g);
        }
    }
    __syncthreads();
}

// ---------------- split-bf16 helpers (validated in R11/R12) --------------------
__device__ __forceinline__ void bsplit4(float4 v, ull& hi, ull& lo){
    __nv_bfloat16 h0 = __float2bfloat16_rn(v.x);
    __nv_bfloat16 h1 = __float2bfloat16_rn(v.y);
    __nv_bfloat16 h2 = __float2bfloat16_rn(v.z);
    __nv_bfloat16 h3 = __float2bfloat16_rn(v.w);
    __nv_bfloat16 l0 = __float2bfloat16_rn(v.x - __bfloat162float(h0));
    __nv_bfloat16 l1 = __float2bfloat16_rn(v.y - __bfloat162float(h1));
    __nv_bfloat16 l2 = __float2bfloat16_rn(v.z - __bfloat162float(h2));
    __nv_bfloat16 l3 = __float2bfloat16_rn(v.w - __bfloat162float(h3));
    hi = (ull)__bfloat16_as_ushort(h0) | ((ull)__bfloat16_as_ushort(h1) << 16)
       | ((ull)__bfloat16_as_ushort(h2) << 32) | ((ull)__bfloat16_as_ushort(h3) << 48);
    lo = (ull)__bfloat16_as_ushort(l0) | ((ull)__bfloat16_as_ushort(l1) << 16)
       | ((ull)__bfloat16_as_ushort(l2) << 32) | ((ull)__bfloat16_as_ushort(l3) << 48);
}
__device__ __forceinline__ void mma16816(float* c, const unsigned* a, const unsigned* b){
    asm volatile(
        "mma.sync.aligned.m16n8k16.row.col.f32.bf16.bf16.f32 "
        "{%0,%1,%2,%3}, {%4,%5,%6,%7}, {%8,%9}, {%0,%1,%2,%3};"
        : "+f"(c[0]), "+f"(c[1]), "+f"(c[2]), "+f"(c[3])
        : "r"(a[0]), "r"(a[1]), "r"(a[2]), "r"(a[3]), "r"(b[0]), "r"(b[1]));
}
__device__ __forceinline__ void ldsm4(unsigned* r, const void* p){
    unsigned a = (unsigned)__cvta_generic_to_shared(p);
    asm volatile("ldmatrix.sync.aligned.m8n8.x4.shared.b16 {%0,%1,%2,%3}, [%4];"
                 : "=r"(r[0]), "=r"(r[1]), "=r"(r[2]), "=r"(r[3]) : "r"(a));
}

// ---------------- fused conv + weighted-sum (reads inputs ONCE) ---------------
__global__ __launch_bounds__(256) void k_conv_vec(const float* __restrict__ inp,
                                                  const float* __restrict__ conv_w,
                                                  const float* __restrict__ conv_b){
    extern __shared__ float tile[];          // P_*D_ = 16384 floats = 64KB
    __shared__ float cw[D_];
    __shared__ float convp[P_];
    int bs = blockIdx.x;
    int tid = threadIdx.x;
    const float4* src4 = (const float4*)(inp + (size_t)bs*P_*D_);
    float4* t4 = (float4*)tile;
    for (int i = tid; i < D_; i += 256) cw[i] = conv_w[i];
    for (int i = tid; i < P_*D_/4; i += 256) t4[i] = src4[i];
    __syncthreads();
    int wid = tid >> 5, lane = tid & 31;
    float cb = conv_b[0];
    for (int p = wid; p < P_; p += 8){
        float s = 0.f;
        for (int d = lane; d < D_; d += 32) s += tile[p*D_+d]*cw[d];
        #pragma unroll
        for (int o = 16; o > 0; o >>= 1) s += __shfl_xor_sync(0xffffffffu, s, o);
        if (lane == 0) convp[p] = s + cb;
    }
    __syncthreads();
    for (int d = tid; d < D_; d += 256){
        float acc = 0.f;
        #pragma unroll
        for (int p = 0; p < P_; p++) acc += convp[p]*tile[p*D_+d];
        g_vec[(size_t)bs*D_ + d] = acc;
    }
}

// ---------------- split-bf16 HMMA GEMM v2 (R13-proven, verbatim) ---------------
__global__ __launch_bounds__(256) void k_bgemm(const float* __restrict__ A,
                                               const float* __restrict__ Bw,
                                               const float* __restrict__ Bw2,
                                               float* __restrict__ C,
                                               int M, int N, int K,
                                               const float* __restrict__ bias,
                                               const float* __restrict__ bias2,
                                               int doClip, int permA){
    __shared__ __align__(16) unsigned short sAh[2][128*GST];
    __shared__ __align__(16) unsigned short sAl[2][128*GST];
    __shared__ __align__(16) unsigned short sBh[2][64*GST];
    __shared__ __align__(16) unsigned short sBl[2][64*GST];

    int tid = threadIdx.x;
    int wid = tid >> 5, lane = tid & 31;
    if (blockIdx.z){ Bw = Bw2; bias = bias2; C += (size_t)M*N; }
    int mbase = blockIdx.y * 128;
    int nbase = blockIdx.x * 64;

    int ia0 = tid*2, ia1 = tid*2 + 1;
    int ra0 = ia0 >> 2, ca0 = (ia0 & 3)*4;
    int ra1 = ia1 >> 2, ca1 = (ia1 & 3)*4;
    int rb  = tid >> 2, cb = (tid & 3)*4;
    int ga0 = mbase + ra0, ga1 = mbase + ra1;
    if (permA){ ga0 = (ga0 & 63)*64 + (ga0 >> 6); ga1 = (ga1 & 63)*64 + (ga1 >> 6); }
    const float* ApR0 = A + (size_t)ga0*K + ca0;
    const float* ApR1 = A + (size_t)ga1*K + ca1;
    const float* BpR  = Bw + (size_t)(nbase + rb)*K + cb;

    int m0 = (wid & 3) * 32;
    int n0 = (wid >> 2) * 32;
    int g = lane >> 2, tg = lane & 3;

    int rin = lane & 7, sel = lane >> 3;
    int offA0 = (m0 + (sel & 1)*8 + rin)*GST + (sel >> 1)*8;
    int offA1 = offA0 + 16*GST;
    int offB0 = (n0 + (sel >> 1)*8 + rin)*GST + (sel & 1)*8;
    int offB1 = offB0 + 16*GST;

    float acc[2][4][4];
    #pragma unroll
    for (int i = 0; i < 2; i++)
        #pragma unroll
        for (int jn = 0; jn < 4; jn++)
            #pragma unroll
            for (int e = 0; e < 4; e++) acc[i][jn][e] = 0.f;

    int nk = K >> 4;
    float4 av0 = *(const float4*)ApR0;
    float4 av1 = *(const float4*)ApR1;
    float4 bv  = *(const float4*)BpR;
    {
        ull hi, lo;
        bsplit4(av0, hi, lo);
        *(ull*)&sAh[0][ra0*GST + ca0] = hi;  *(ull*)&sAl[0][ra0*GST + ca0] = lo;
        bsplit4(av1, hi, lo);
        *(ull*)&sAh[0][ra1*GST + ca1] = hi;  *(ull*)&sAl[0][ra1*GST + ca1] = lo;
        bsplit4(bv, hi, lo);
        *(ull*)&sBh[0][rb*GST + cb] = hi;    *(ull*)&sBl[0][rb*GST + cb] = lo;
    }
    __syncthreads();

    for (int kt = 0; kt < nk; kt++){
        int cur = kt & 1;
        if (kt + 1 < nk){
            av0 = *(const float4*)(ApR0 + (kt+1)*16);
            av1 = *(const float4*)(ApR1 + (kt+1)*16);
            bv  = *(const float4*)(BpR  + (kt+1)*16);
        }

        unsigned ah[2][4], al[2][4], bh[2][4], bl[2][4];
        ldsm4(ah[0], &sAh[cur][offA0]);
        ldsm4(ah[1], &sAh[cur][offA1]);
        ldsm4(al[0], &sAl[cur][offA0]);
        ldsm4(al[1], &sAl[cur][offA1]);
        ldsm4(bh[0], &sBh[cur][offB0]);
        ldsm4(bh[1], &sBh[cur][offB1]);
        ldsm4(bl[0], &sBl[cur][offB0]);
        ldsm4(bl[1], &sBl[cur][offB1]);

        #pragma unroll
        for (int i = 0; i < 2; i++){
            #pragma unroll
            for (int jn = 0; jn < 4; jn++){
                const unsigned* pbh = &bh[jn >> 1][(jn & 1)*2];
                const unsigned* pbl = &bl[jn >> 1][(jn & 1)*2];
                mma16816(acc[i][jn], ah[i], pbh);
                mma16816(acc[i][jn], ah[i], pbl);
                mma16816(acc[i][jn], al[i], pbh);
            }
        }

        if (kt + 1 < nk){
            int nxt = cur ^ 1;
            ull hi, lo;
            bsplit4(av0, hi, lo);
            *(ull*)&sAh[nxt][ra0*GST + ca0] = hi;  *(ull*)&sAl[nxt][ra0*GST + ca0] = lo;
            bsplit4(av1, hi, lo);
            *(ull*)&sAh[nxt][ra1*GST + ca1] = hi;  *(ull*)&sAl[nxt][ra1*GST + ca1] = lo;
            bsplit4(bv, hi, lo);
            *(ull*)&sBh[nxt][rb*GST + cb] = hi;    *(ull*)&sBl[nxt][rb*GST + cb] = lo;
        }
        __syncthreads();
    }

    #pragma unroll
    for (int i = 0; i < 2; i++){
        int row0 = mbase + m0 + i*16 + g;
        int row1 = row0 + 8;
        #pragma unroll
        for (int jn = 0; jn < 4; jn++){
            int col = nbase + n0 + jn*8 + tg*2;
            float2 v0 = make_float2(acc[i][jn][0], acc[i][jn][1]);
            float2 v1 = make_float2(acc[i][jn][2], acc[i][jn][3]);
            if (bias){
                float2 bb = *(const float2*)&bias[col];
                v0.x += bb.x; v0.y += bb.y;
                v1.x += bb.x; v1.y += bb.y;
            }
            if (doClip){
                v0.x = fminf(fmaxf(v0.x,-1.f),1.f); v0.y = fminf(fmaxf(v0.y,-1.f),1.f);
                v1.x = fminf(fmaxf(v1.x,-1.f),1.f); v1.y = fminf(fmaxf(v1.y,-1.f),1.f);
            }
            *(float2*)&C[(size_t)row0*N + col] = v0;
            *(float2*)&C[(size_t)row1*N + col] = v1;
        }
    }
}

// ---------------- persistent bidirectional GRU v10 ----------------------------
// R12 HMMA recurrence, but: h lives ONLY in states (no g_h2 double buffer),
// fence-free acq/rel barrier, no init barrier, no final-step barrier.
__global__ __launch_bounds__(256) void k_gru(const float* __restrict__ w_hh_f,
                                             const float* __restrict__ w_hh_b,
                                             const float* __restrict__ b_hh_f,
                                             const float* __restrict__ b_hh_b,
                                             float* __restrict__ states){
    extern __shared__ unsigned short smu[];
    unsigned short* wHi = smu;                       // 96*WPAD
    unsigned short* wLo = smu + 96*WPAD;             // 96*WPAD
    unsigned short* hHi = smu + 192*WPAD;            // 16*WPAD
    unsigned short* hLo = hHi + 16*WPAD;             // 16*WPAD
    float* epi = (float*)hHi;                        // 96*16 floats, reused post-mma

    int blk = blockIdx.x;        // 128
    int dir = blk >> 6;
    int rr = blk & 63;
    int jc = rr >> 2, bq = rr & 3;
    int jbase = jc * 32;
    int bbase = bq * 16;
    int grp = dir*4 + bq;        // 0..7
    const float* whh = dir ? w_hh_b : w_hh_f;
    const float* bhh = dir ? b_hh_b : b_hh_f;
    const float* xg = g_xg[dir];
    int tid = threadIdx.x;
    int wid = tid >> 5, lane = tid & 31;
    int g = lane >> 2, tg = lane & 3;
    int jp = tid >> 3;           // 0..31
    int bp = tid & 7;            // 0..7
    int j  = jbase + jp;
    int b0 = bbase + bp*2;

    // ---- one-time: load + split weights (rows: gate*32 + jl) ----
    {
        const float4* w4 = (const float4*)whh;
        for (int idx = tid; idx < 96*128; idx += 256){
            int row = idx >> 7;          // gate*32 + jl
            int kq = idx & 127;
            int gg = row >> 5, jl = row & 31;
            float4 v = w4[(size_t)(gg*H_ + jbase + jl)*128 + kq];
            ull hi, lo;
            bsplit4(v, hi, lo);
            *(ull*)&wHi[row*WPAD + kq*4] = hi;
            *(ull*)&wLo[row*WPAD + kq*4] = lo;
        }
    }

    float bhr = bhh[j], bhz = bhh[H_+j], bhn = bhh[2*H_+j];

    // preload xg for t=0
    int tidx0 = dir ? (S_-1) : 0;
    const float* xA0 = xg + ((size_t)(tidx0*B_ + b0))*H3_;
    const float* xB0 = xA0 + H3_;
    float xr0 = xA0[j], xz0 = xA0[H_+j], xn0 = xA0[2*H_+j];
    float xr1 = xB0[j], xz1 = xB0[H_+j], xn1 = xB0[2*H_+j];

    int m0r = wid * 16;          // mma warp's row base (wid < 6)

    for (int t = 0; t < S_; t++){
        int tidx = dir ? (S_-1-t) : t;
        int ptidx = dir ? (S_-t) : (t-1);   // previous output time (valid t>=1)

        // stage h from states (prev tidx) split into bf16 hi/lo; t=0 -> zeros
        float hp0, hp1;
        if (t == 0){
            #pragma unroll
            for (int i = 0; i < 8; i++){
                int gi = tid + (i << 8);
                int bb = gi >> 7, kq = gi & 127;
                *(ull*)&hHi[bb*WPAD + kq*4] = 0ULL;
                *(ull*)&hLo[bb*WPAD + kq*4] = 0ULL;
            }
            hp0 = 0.f; hp1 = 0.f;
        } else {
            #pragma unroll
            for (int i = 0; i < 8; i++){
                int gi = tid + (i << 8);
                int bb = gi >> 7, kq = gi & 127;
                const float4* src = (const float4*)(states
                    + ((size_t)((bbase+bb)*S_ + ptidx))*(2*H_) + dir*H_);
                ull hi, lo;
                bsplit4(src[kq], hi, lo);
                *(ull*)&hHi[bb*WPAD + kq*4] = hi;
                *(ull*)&hLo[bb*WPAD + kq*4] = lo;
            }
            hp0 = states[((size_t)b0*S_ + ptidx)*(2*H_) + dir*H_ + j];
            hp1 = states[((size_t)(b0+1)*S_ + ptidx)*(2*H_) + dir*H_ + j];
        }
        // next xg issued early (hidden under mma)
        float nxr0=0,nxz0=0,nxn0=0,nxr1=0,nxz1=0,nxn1=0;
        if (t + 1 < S_){
            int ntidx = dir ? (S_-2-t) : (t+1);
            const float* nA = xg + ((size_t)(ntidx*B_ + b0))*H3_;
            const float* nB = nA + H3_;
            nxr0 = nA[j]; nxz0 = nA[H_+j]; nxn0 = nA[2*H_+j];
            nxr1 = nB[j]; nxz1 = nB[H_+j]; nxn1 = nB[2*H_+j];
        }
        __syncthreads();

        float acc0[4] = {0.f,0.f,0.f,0.f};
        float acc1[4] = {0.f,0.f,0.f,0.f};
        if (wid < 6){
            int rA0 = (m0r + g)*WPAD;
            int rA8 = (m0r + g + 8)*WPAD;
            int rB0 = g*WPAD;
            int rB8 = (8 + g)*WPAD;
            #pragma unroll 4
            for (int kc = 0; kc < 32; kc++){
                int kb = kc*16 + tg*2;
                unsigned ah[4], al[4], b0h[2], b0l[2], b1h[2], b1l[2];
                ah[0] = *(const unsigned*)&wHi[rA0 + kb];
                ah[1] = *(const unsigned*)&wHi[rA8 + kb];
                ah[2] = *(const unsigned*)&wHi[rA0 + kb + 8];
                ah[3] = *(const unsigned*)&wHi[rA8 + kb + 8];
                al[0] = *(const unsigned*)&wLo[rA0 + kb];
                al[1] = *(const unsigned*)&wLo[rA8 + kb];
                al[2] = *(const unsigned*)&wLo[rA0 + kb + 8];
                al[3] = *(const unsigned*)&wLo[rA8 + kb + 8];
                b0h[0] = *(const unsigned*)&hHi[rB0 + kb];
                b0h[1] = *(const unsigned*)&hHi[rB0 + kb + 8];
                b0l[0] = *(const unsigned*)&hLo[rB0 + kb];
                b0l[1] = *(const unsigned*)&hLo[rB0 + kb + 8];
                b1h[0] = *(const unsigned*)&hHi[rB8 + kb];
                b1h[1] = *(const unsigned*)&hHi[rB8 + kb + 8];
                b1l[0] = *(const unsigned*)&hLo[rB8 + kb];
                b1l[1] = *(const unsigned*)&hLo[rB8 + kb + 8];
                mma16816(acc0, ah, b0h);
                mma16816(acc0, ah, b0l);
                mma16816(acc0, al, b0h);
                mma16816(acc1, ah, b1h);
                mma16816(acc1, ah, b1l);
                mma16816(acc1, al, b1h);
            }
        }
        __syncthreads();   // all hHi/hLo reads done -> safe to reuse as epi

        if (wid < 6){
            int r0 = (m0r + g)*16;
            int r8 = (m0r + g + 8)*16;
            epi[r0 + tg*2]          = acc0[0];
            epi[r0 + tg*2 + 1]      = acc0[1];
            epi[r8 + tg*2]          = acc0[2];
            epi[r8 + tg*2 + 1]      = acc0[3];
            epi[r0 + 8 + tg*2]      = acc1[0];
            epi[r0 + 8 + tg*2 + 1]  = acc1[1];
            epi[r8 + 8 + tg*2]      = acc1[2];
            epi[r8 + 8 + tg*2 + 1]  = acc1[3];
        }
        __syncthreads();

        float sr0 = epi[jp*16 + bp*2],        sr1 = epi[jp*16 + bp*2 + 1];
        float sz0 = epi[(32+jp)*16 + bp*2],   sz1 = epi[(32+jp)*16 + bp*2 + 1];
        float sn0 = epi[(64+jp)*16 + bp*2],   sn1 = epi[(64+jp)*16 + bp*2 + 1];

        float r0 = 1.f/(1.f+expf(-(xr0 + sr0 + bhr)));
        float r1 = 1.f/(1.f+expf(-(xr1 + sr1 + bhr)));
        float z0 = 1.f/(1.f+expf(-(xz0 + sz0 + bhz)));
        float z1 = 1.f/(1.f+expf(-(xz1 + sz1 + bhz)));
        float n0 = tanhf(xn0 + r0*(sn0 + bhn));
        float n1 = tanhf(xn1 + r1*(sn1 + bhn));
        float h0 = (1.f-z0)*n0 + z0*hp0;
        float h1 = (1.f-z1)*n1 + z1*hp1;

        states[((size_t)b0*S_ + tidx)*(2*H_) + dir*H_ + j]     = h0;
        states[((size_t)(b0+1)*S_ + tidx)*(2*H_) + dir*H_ + j] = h1;

        if (t + 1 < S_) gbar_grp(grp);

        xr0=nxr0; xz0=nxz0; xn0=nxn0; xr1=nxr1; xz1=nxz1; xn1=nxn1;
    }
}

// ---------------- alpha = m1 @ att_w2^T, softmax over S -----------------------
__global__ __launch_bounds__(256) void k_alpha(const float* __restrict__ att_w2,
                                               float* __restrict__ alpha_out){
    __shared__ float w2s[NH_*A_];
    __shared__ float al[NH_*S_];
    int b = blockIdx.x, tid = threadIdx.x;
    for (int i = tid; i < NH_*A_; i += 256) w2s[i] = att_w2[i];
    __syncthreads();
    int s = tid >> 2, h = tid & 3;
    const float* m1r = g_m1 + ((size_t)(b*S_ + s))*A_;
    float acc = 0.f;
    #pragma unroll 4
    for (int k = 0; k < A_; k++) acc += m1r[k]*w2s[h*A_+k];
    al[h*S_+s] = acc;
    __syncthreads();
    int wid = tid >> 5, lane = tid & 31;
    if (wid < NH_){
        float v0 = al[wid*S_+lane], v1 = al[wid*S_+lane+32];
        float mx = fmaxf(v0, v1);
        #pragma unroll
        for (int o = 16; o > 0; o >>= 1) mx = fmaxf(mx, __shfl_xor_sync(0xffffffffu, mx, o));
        float e0 = expf(v0-mx), e1 = expf(v1-mx);
        float sm = e0 + e1;
        #pragma unroll
        for (int o = 16; o > 0; o >>= 1) sm += __shfl_xor_sync(0xffffffffu, sm, o);
        float inv = 1.f/sm;
        alpha_out[(b*NH_+wid)*S_ + lane]      = e0*inv;
        alpha_out[(b*NH_+wid)*S_ + lane + 32] = e1*inv;
    }
}

// ---------------- context = alpha @ states ------------------------------------
__global__ __launch_bounds__(512) void k_context(const float* __restrict__ states,
                                                 const float* __restrict__ alpha_in,
                                                 float* __restrict__ context){
    __shared__ float als[NH_*S_];
    int b = blockIdx.x, tid = threadIdx.x;
    if (tid < NH_*S_) als[tid] = alpha_in[b*NH_*S_ + tid];
    __syncthreads();
    float a0[NH_], a1[NH_];
    #pragma unroll
    for (int h = 0; h < NH_; h++){ a0[h] = 0.f; a1[h] = 0.f; }
    const float* st = states + (size_t)b*S_*2*H_;
    for (int s = 0; s < S_; s++){
        float v0 = st[s*2*H_ + tid];
        float v1 = st[s*2*H_ + H_ + tid];
        #pragma unroll
        for (int h = 0; h < NH_; h++){
            float a = als[h*S_+s];
            a0[h] += a*v0; a1[h] += a*v1;
        }
    }
    float* cb = context + (size_t)b*NH_*2*H_;
    #pragma unroll
    for (int h = 0; h < NH_; h++){
        cb[h*2*H_ + tid]      = a0[h];
        cb[h*2*H_ + H_ + tid] = a1[h];
    }
}

// ---------------- final linear + softmax --------------------------------------
__global__ __launch_bounds__(512) void k_final(const float* __restrict__ context,
                                               const float* __restrict__ lin_w,
                                               const float* __restrict__ lin_b,
                                               float* __restrict__ out){
    __shared__ float red[OUT_];
    int b = blockIdx.x, tid = threadIdx.x, w = tid >> 5, lane = tid & 31;
    const float* cx = context + (size_t)b*4096;
    const float* lw = lin_w + (size_t)w*4096;
    float acc = 0.f;
    for (int k = lane; k < 4096; k += 32) acc += cx[k]*lw[k];
    #pragma unroll
    for (int o = 16; o > 0; o >>= 1) acc += __shfl_xor_sync(0xffffffffu, acc, o);
    if (lane == 0) red[w] = acc + lin_b[w];
    __syncthreads();
    if (tid < 32){
        float v = (lane < OUT_) ? red[lane] : -1e30f;
        float mx = v;
        #pragma unroll
        for (int o = 16; o > 0; o >>= 1) mx = fmaxf(mx, __shfl_xor_sync(0xffffffffu, mx, o));
        float e = (lane < OUT_) ? expf(v - mx) : 0.f;
        float sm = e;
        #pragma unroll
        for (int o = 16; o > 0; o >>= 1) sm += __shfl_xor_sync(0xffffffffu, sm, o);
        if (lane < OUT_) out[b*OUT_ + lane] = e/sm;
    }
}

// ---------------- launch ------------------------------------------------------
extern "C" void kernel_launch(void* const* d_in, const int* in_sizes, int n_in,
                              void* d_out, int out_size){
    const float* inputs  = (const float*)d_in[0];
    const float* conv_w  = (const float*)d_in[2];
    const float* conv_b  = (const float*)d_in[3];
    const float* w_embed = (const float*)d_in[4];
    const float* w_ih_f  = (const float*)d_in[5];
    const float* w_hh_f  = (const float*)d_in[6];
    const float* b_ih_f  = (const float*)d_in[7];
    const float* b_hh_f  = (const float*)d_in[8];
    const float* w_ih_b  = (const float*)d_in[9];
    const float* w_hh_b  = (const float*)d_in[10];
    const float* b_ih_b  = (const float*)d_in[11];
    const float* b_hh_b  = (const float*)d_in[12];
    const float* att_w1  = (const float*)d_in[13];
    const float* att_w2  = (const float*)d_in[14];
    const float* lin_w   = (const float*)d_in[15];
    const float* lin_b   = (const float*)d_in[16];

    float* out     = (float*)d_out;
    float* states  = out + STATES_OFF;
    float* context = out + CONTEXT_OFF;
    float* alpha   = out + ALPHA_OFF;

    void *p_vec, *p_emb, *p_xg, *p_m1;
    cudaGetSymbolAddress(&p_vec, g_vec);
    cudaGetSymbolAddress(&p_emb, g_emb);
    cudaGetSymbolAddress(&p_xg,  g_xg);
    cudaGetSymbolAddress(&p_m1,  g_m1);
    float* vec = (float*)p_vec;
    float* emb = (float*)p_emb;
    float* xg0 = (float*)p_xg;
    float* m1  = (float*)p_m1;

    const int conv_smem = P_*D_*4;                       // 65536
    const int gru_smem  = (192*WPAD + 32*WPAD) * 2;      // 231168
    cudaFuncSetAttribute(k_conv_vec, cudaFuncAttributeMaxDynamicSharedMemorySize, conv_smem);
    cudaFuncSetAttribute(k_gru,      cudaFuncAttributeMaxDynamicSharedMemorySize, gru_smem);

    // 1) conv + weighted-sum (inputs read once)
    k_conv_vec<<<BS_, 256, conv_smem>>>(inputs, conv_w, conv_b);
    // 2) emb = clip(vec @ w_embed^T)  [split-bf16 HMMA + ldmatrix]
    k_bgemm<<<dim3(E_/64, BS_/128, 1), 256>>>(vec, w_embed, w_embed, emb,
                                              BS_, E_, D_, nullptr, nullptr, 1, 0);
    // 3) xg = emb([S,B] permuted) @ w_ih^T + b_ih, BOTH dirs via grid.z
    k_bgemm<<<dim3(H3_/64, BS_/128, 2), 256>>>(emb, w_ih_f, w_ih_b, xg0,
                                               BS_, H3_, E_, b_ih_f, b_ih_b, 0, 1);
    // 4) persistent bidirectional GRU (HMMA recurrence, fence-free) -> states
    k_gru<<<128, 256, gru_smem>>>(w_hh_f, w_hh_b, b_hh_f, b_hh_b, states);
    // 5) m1 = clip(states @ att_w1^T)  [split-bf16 HMMA + ldmatrix]
    k_bgemm<<<dim3(A_/64, BS_/128, 1), 256>>>(states, att_w1, att_w1, m1,
                                              BS_, A_, 2*H_, nullptr, nullptr, 1, 0);
    // 6) alpha = softmax_S(m1 @ att_w2^T), transposed to [B,NH,S]
    k_alpha<<<B_, 256>>>(att_w2, alpha);
    // 7) context
    k_context<<<B_, 512>>>(states, alpha, context);
    // 8) out = softmax(context @ lin_w^T + lin_b)
    k_final<<<B_, 512>>>(context, lin_w, lin_b, out);
}